// round 13
// baseline (speedup 1.0000x reference)
#include <cuda_runtime.h>
#include <cuda_fp16.h>
#include <cstdint>

#define S_LEN 2048
#define EMB   2048
#define NH    16
#define DH    128
#define BATCH 2
#define MROWS (BATCH * S_LEN)   // 4096
#define GK    2048              // K for both projection GEMMs

// ---------------------------------------------------------------------------
// Device scratch (no cudaMalloc allowed)
// ---------------------------------------------------------------------------
__device__ __half g_a16[(size_t)MROWS * GK];              // A operand (x, then attn-out), fp16
__device__ __half g_wq[(size_t)(3 * EMB) * GK];           // W_qkv^T fp16 [6144,2048]
__device__ __half g_wo[(size_t)EMB * GK];                 // W_out^T fp16 [2048,2048]
// per-head Q/K/V fp16 (single-rounded), layout [B, H, S, DH]
// Q pre-scaled by log2(e)/sqrt(dh) so softmax runs in exp2 domain directly.
#define QKV_ELEMS ((size_t)BATCH * NH * S_LEN * DH)
__device__ __half g_q16[QKV_ELEMS];
__device__ __half g_k16[QKV_ELEMS];
__device__ __half g_v16[QKV_ELEMS];

// ---------------------------------------------------------------------------
// PTX helpers (plain sm_80+ instructions only)
// ---------------------------------------------------------------------------
__device__ __forceinline__ uint32_t smem_to_u32(const void* p) {
    uint32_t a;
    asm("{ .reg .u64 t; cvta.to.shared.u64 t, %1; cvt.u32.u64 %0, t; }"
        : "=r"(a) : "l"(p));
    return a;
}

__device__ __forceinline__ void cp_async16(uint32_t saddr, const void* gaddr) {
    asm volatile("cp.async.cg.shared.global [%0], [%1], 16;"
        :: "r"(saddr), "l"(gaddr) : "memory");
}
#define CP_COMMIT() asm volatile("cp.async.commit_group;" ::: "memory")
#define CP_WAIT(n)  asm volatile("cp.async.wait_group %0;" :: "n"(n) : "memory")

__device__ __forceinline__ void ldsm_x4(uint32_t* r, uint32_t addr) {
    asm volatile("ldmatrix.sync.aligned.m8n8.x4.shared.b16 {%0,%1,%2,%3}, [%4];"
        : "=r"(r[0]), "=r"(r[1]), "=r"(r[2]), "=r"(r[3]) : "r"(addr));
}
__device__ __forceinline__ void ldsm_x4_t(uint32_t* r, uint32_t addr) {
    asm volatile("ldmatrix.sync.aligned.m8n8.x4.trans.shared.b16 {%0,%1,%2,%3}, [%4];"
        : "=r"(r[0]), "=r"(r[1]), "=r"(r[2]), "=r"(r[3]) : "r"(addr));
}

// fp16 MMA (all tensor work)
__device__ __forceinline__ void mma16816h(float* d, const uint32_t* a,
                                          const uint32_t* b) {
    asm volatile(
        "mma.sync.aligned.m16n8k16.row.col.f32.f16.f16.f32 "
        "{%0,%1,%2,%3}, {%4,%5,%6,%7}, {%8,%9}, {%0,%1,%2,%3};"
        : "+f"(d[0]), "+f"(d[1]), "+f"(d[2]), "+f"(d[3])
        : "r"(a[0]), "r"(a[1]), "r"(a[2]), "r"(a[3]), "r"(b[0]), "r"(b[1]));
}

// Fast 2^t on FMA/ALU pipes only (no MUFU, no CVT). |rel err| < 3e-6.
__device__ __forceinline__ float exp2_fast(float t) {
    t = fmaxf(t, -126.0f);
    const float MAGIC = 12582912.0f;          // 2^23 + 2^22
    float z = t + MAGIC;
    int i = __float_as_int(z);
    float r = z - MAGIC;
    float f = t - r;                          // f in [-0.5, 0.5]
    float p = 1.3333558146e-3f;
    p = fmaf(p, f, 9.6181291076e-3f);
    p = fmaf(p, f, 5.5504108664e-2f);
    p = fmaf(p, f, 2.4022650696e-1f);
    p = fmaf(p, f, 6.9314718056e-1f);
    p = fmaf(p, f, 1.0f);
    int eb = (i + (127 - 0x4B400000)) << 23;
    return p * __int_as_float(eb);
}

__device__ __forceinline__ uint32_t h2u(__half2 v) {
    return *(uint32_t*)&v;
}

#define SOFTMAX_SCALE 0.12751744f     // log2(e) / sqrt(128)

// ---------------------------------------------------------------------------
// Conversion kernels
// ---------------------------------------------------------------------------
__global__ __launch_bounds__(256) void to_half_kernel(
    const float* __restrict__ in, __half* __restrict__ out, int n)
{
    int i = blockIdx.x * blockDim.x + threadIdx.x;
    int stride = gridDim.x * blockDim.x;
    for (; i < n; i += stride) out[i] = __float2half(in[i]);
}

// W[K,N] row-major -> T[N,K] fp16 (single rounding)
__global__ __launch_bounds__(256) void transpose_half_kernel(
    const float* __restrict__ W, __half* __restrict__ T, int K, int N)
{
    __shared__ float t[32][33];
    const int nb = blockIdx.x * 32;
    const int kb = blockIdx.y * 32;
    const int x = threadIdx.x, y = threadIdx.y;   // block (32,8)
    #pragma unroll
    for (int j = 0; j < 32; j += 8)
        t[y + j][x] = W[(size_t)(kb + y + j) * N + nb + x];
    __syncthreads();
    #pragma unroll
    for (int j = 0; j < 32; j += 8)
        T[(size_t)(nb + y + j) * K + kb + x] = __float2half(t[x][y + j]);
}

// ---------------------------------------------------------------------------
// fp16 HMMA mainloop: C = A*B^T + bias.
// Block tile 256(M) x 128(N), 8 warps (4x2), warp tile 64x64, K-chunk 64,
// 2-stage double buffer. 4 MMA per ldsm_x4.
// ---------------------------------------------------------------------------
#define GBK   64
#define NCHUNK (GK / GBK)
#define ATB   32768                  // A: 256 rows x 128B
#define BTB   16384                  // B: 128 rows x 128B
#define STAGE (ATB + BTB)            // 48 KB
#define GEMM_SMEM (2 * STAGE)        // 96 KB

template <typename Epilogue>
__device__ __forceinline__ void gemm_mainloop(
    char* gsm,
    const __half* __restrict__ A, const __half* __restrict__ B,
    const float* __restrict__ bias, int bx, int by, Epilogue epi)
{
    const uint32_t sb = smem_to_u32(gsm);
    const int tid = threadIdx.x;
    const int w = tid >> 5, l = tid & 31;
    const int warp_m = w >> 1, warp_n = w & 1;   // 4 x 2 warp grid

    const __half* gA = A + (size_t)(by * 256) * GK;
    const __half* gB = B + (size_t)(bx * 128) * GK;

    float acc[4][8][4];
    #pragma unroll
    for (int nt = 0; nt < 8; nt++) {
        const int n = bx * 128 + warp_n * 64 + nt * 8 + ((l & 3) << 1);
        const float b0 = bias[n], b1 = bias[n + 1];
        #pragma unroll
        for (int mt = 0; mt < 4; mt++) {
            acc[mt][nt][0] = b0; acc[mt][nt][1] = b1;
            acc[mt][nt][2] = b0; acc[mt][nt][3] = b1;
        }
    }

    auto load_chunk = [&](int kt) {
        const uint32_t st = sb + (kt & 1) * STAGE;
        const size_t kofs = (size_t)kt * GBK;
        // A: 256 rows x 8 units = 2048 units
        {
            const char* g = (const char*)(gA + kofs);
            #pragma unroll
            for (int j = 0; j < 8; j++) {
                const int u = tid + 256 * j;
                const int r = u >> 3;
                const int cu = u & 7;
                const uint32_t off = r * 128 + ((cu ^ (r & 7)) << 4);
                cp_async16(st + off, g + (size_t)r * (GK * 2) + (cu << 4));
            }
        }
        // B: 128 rows x 8 units = 1024 units
        {
            const char* g = (const char*)(gB + kofs);
            #pragma unroll
            for (int j = 0; j < 4; j++) {
                const int u = tid + 256 * j;
                const int r = u >> 3;
                const int cu = u & 7;
                const uint32_t off = r * 128 + ((cu ^ (r & 7)) << 4);
                cp_async16(st + ATB + off, g + (size_t)r * (GK * 2) + (cu << 4));
            }
        }
        CP_COMMIT();
    };

    load_chunk(0);

    for (int kt = 0; kt < NCHUNK; kt++) {
        if (kt + 1 < NCHUNK) { load_chunk(kt + 1); CP_WAIT(1); }
        else                 { CP_WAIT(0); }
        __syncthreads();

        const uint32_t st = sb + (kt & 1) * STAGE;
        const uint32_t sA = st, sB = st + ATB;

        #pragma unroll
        for (int kk = 0; kk < 4; kk++) {
            const int kb = kk * 32;

            uint32_t af[4][4];
            #pragma unroll
            for (int mt = 0; mt < 4; mt++) {
                const int row = warp_m * 64 + mt * 16 + (l & 15);
                const int bc = kb + ((l >> 4) << 4);
                const uint32_t off = row * 128 + (bc ^ ((row & 7) << 4));
                ldsm_x4(af[mt], sA + off);
            }

            uint32_t bf[4][4];
            #pragma unroll
            for (int np = 0; np < 4; np++) {
                const int g = l >> 3, idx = l & 7;
                const int row = warp_n * 64 + np * 16 + ((g >> 1) << 3) + idx;
                const int bc = kb + ((g & 1) << 4);
                const uint32_t off = row * 128 + (bc ^ ((row & 7) << 4));
                ldsm_x4(bf[np], sB + off);
            }

            #pragma unroll
            for (int mt = 0; mt < 4; mt++)
                #pragma unroll
                for (int nt = 0; nt < 8; nt++)
                    mma16816h(acc[mt][nt], af[mt], &bf[nt >> 1][(nt & 1) * 2]);
        }
        __syncthreads();
    }

    epi(acc, warp_m, warp_n, l);
}

// GEMM2: plain fp32 output C = A*B^T + bias
__global__ __launch_bounds__(256, 1) void gemm_mma_kernel(
    int N,
    const __half* __restrict__ A, const __half* __restrict__ B,
    const float* __restrict__ bias, float* __restrict__ C)
{
    extern __shared__ char gsm[];
    const int bx = blockIdx.x, by = blockIdx.y;
    gemm_mainloop(gsm, A, B, bias, bx, by,
        [&](float acc[4][8][4], int warp_m, int warp_n, int l) {
            #pragma unroll
            for (int mt = 0; mt < 4; mt++) {
                const int m = by * 256 + warp_m * 64 + mt * 16 + (l >> 2);
                float* c0 = C + (size_t)m * N + bx * 128 + warp_n * 64 + ((l & 3) << 1);
                #pragma unroll
                for (int nt = 0; nt < 8; nt++) {
                    *(float2*)(c0 + nt * 8) =
                        make_float2(acc[mt][nt][0], acc[mt][nt][1]);
                    *(float2*)(c0 + (size_t)8 * N + nt * 8) =
                        make_float2(acc[mt][nt][2], acc[mt][nt][3]);
                }
            }
        });
}

// GEMM1 fused: writes per-head fp16 Q (pre-scaled), K, V (single-rounded).
__global__ __launch_bounds__(256, 1) void gemm_qkv_kernel(
    const __half* __restrict__ A, const __half* __restrict__ B,
    const float* __restrict__ bias)
{
    extern __shared__ char gsm[];
    const int bx = blockIdx.x, by = blockIdx.y;
    const int region = bx % 3;        // 0=q, 1=k, 2=v
    const int head   = bx / 3;
    __half* H = (region == 0) ? g_q16 : (region == 1) ? g_k16 : g_v16;
    const float scl = (region == 0) ? SOFTMAX_SCALE : 1.0f;

    gemm_mainloop(gsm, A, B, bias, bx, by,
        [&](float acc[4][8][4], int warp_m, int warp_n, int l) {
            #pragma unroll
            for (int mt = 0; mt < 4; mt++) {
                const int m = by * 256 + warp_m * 64 + mt * 16 + (l >> 2);
                const int b = m >> 11, s = m & (S_LEN - 1);
                const size_t base =
                    (((size_t)(b * NH + head)) * S_LEN + s) * DH;
                #pragma unroll
                for (int nt = 0; nt < 8; nt++) {
                    const int d = warp_n * 64 + nt * 8 + ((l & 3) << 1);
                    const __half2 h0 = __floats2half2_rn(acc[mt][nt][0] * scl,
                                                         acc[mt][nt][1] * scl);
                    const __half2 h1 = __floats2half2_rn(acc[mt][nt][2] * scl,
                                                         acc[mt][nt][3] * scl);
                    *(__half2*)(H + base + d) = h0;
                    *(__half2*)(H + base + (size_t)8 * DH + d) = h1;
                }
            }
        });
}

// ---------------------------------------------------------------------------
// FA2-style tensor-core attention, fp16 single-term, K-tile = 64 keys:
//   QK: Q * K (Q pre-scaled) ; PV: P * V
// 8 warps; each warp owns 16 Q rows (QK 16x64, PV 16x128).
// 3-stage KV pipeline (32 KB/stage), 1 sync per tile.
// ---------------------------------------------------------------------------
#define ATQ 128
#define AKT 64
#define ANT (S_LEN / AKT)             // 32

#define ASM_Q  0                      // 32768 bytes (128 rows x 256B)
#define ASM_KV 32768                  // 3 stages x 32768 (K 16KB | V 16KB)
#define KVSTAGE 32768
#define ATTN_SMEM (32768 + 3 * KVSTAGE)  // 131072

#define SWZ(row, cu) ((row) * 256 + ((((cu) ^ ((row) & 7))) << 4))

__global__ __launch_bounds__(256) void attn_mma_kernel(
    const __half* __restrict__ q16, const __half* __restrict__ k16,
    const __half* __restrict__ v16,
    __half* __restrict__ outA)
{
    extern __shared__ char gsm[];
    const uint32_t sb = smem_to_u32(gsm);
    const int tid = threadIdx.x;
    const int w = tid >> 5, l = tid & 31;
    const int qt = blockIdx.x, h = blockIdx.y, b = blockIdx.z;

    const size_t head = ((size_t)(b * NH + h)) * S_LEN * DH;
    const __half* Q_g = q16 + head + (size_t)qt * ATQ * DH;

    auto load_kv = [&](int t) {
        const uint32_t st = sb + ASM_KV + (t % 3) * KVSTAGE;
        const size_t base = head + (size_t)t * AKT * DH;
        const __half* srcs[2] = {k16 + base, v16 + base};
        #pragma unroll
        for (int a = 0; a < 2; a++) {
            #pragma unroll
            for (int j = 0; j < 4; j++) {       // 64 rows x 16 units = 1024
                const int u = tid + 256 * j;
                const int row = u >> 4, cu = u & 15;
                cp_async16(st + a * 16384 + SWZ(row, cu),
                           (const char*)srcs[a] + (size_t)row * 256 + cu * 16);
            }
        }
        CP_COMMIT();
    };

    // Q loads committed together with KV(0) as group 0.
    #pragma unroll
    for (int j = 0; j < 8; j++) {
        const int u = tid + 256 * j;
        const int row = u >> 4, cu = u & 15;
        cp_async16(sb + ASM_Q + SWZ(row, cu),
                   (const char*)Q_g + (size_t)row * 256 + cu * 16);
    }
    load_kv(0);
    load_kv(1);

    // Wait for group 0 (Q + KV0), then cache ALL Q fragments in registers.
    CP_WAIT(1);
    __syncthreads();
    uint32_t qf[8][4];
    #pragma unroll
    for (int kk = 0; kk < 8; kk++) {
        const int row = w * 16 + (l & 15);
        const int cu = kk * 2 + (l >> 4);
        ldsm_x4(qf[kk], sb + ASM_Q + SWZ(row, cu));
    }

    float m0 = -1e9f, m1 = -1e9f, ls0 = 0.f, ls1 = 0.f;
    float O[16][4];
    #pragma unroll
    for (int nt = 0; nt < 16; nt++)
        #pragma unroll
        for (int c = 0; c < 4; c++) O[nt][c] = 0.f;

    for (int t = 0; t < ANT; t++) {
        if (t > 0) {
            if (t + 1 < ANT) { CP_WAIT(1); } else { CP_WAIT(0); }
            __syncthreads();
        }
        if (t + 2 < ANT) load_kv(t + 2);

        const uint32_t stg = sb + ASM_KV + (t % 3) * KVSTAGE;

        // ---- QK: sacc[8][4], warp tile 16x64, Q from registers -------------
        float sacc[8][4];
        #pragma unroll
        for (int nt = 0; nt < 8; nt++)
            #pragma unroll
            for (int c = 0; c < 4; c++) sacc[nt][c] = 0.f;

        #pragma unroll
        for (int kk = 0; kk < 8; kk++) {
            uint32_t kf[4][4];
            #pragma unroll
            for (int np = 0; np < 4; np++) {
                const int g = l >> 3, idx = l & 7;
                const int krow = np * 16 + ((g >> 1) << 3) + idx;
                const int bcu = kk * 2 + (g & 1);
                ldsm_x4(kf[np], stg + SWZ(krow, bcu));
            }
            #pragma unroll
            for (int nt = 0; nt < 8; nt++)
                mma16816h(sacc[nt], qf[kk], &kf[nt >> 1][(nt & 1) * 2]);
        }

        // ---- softmax in registers (scores already in exp2 domain) ----------
        float mx0 = sacc[0][0], mx1 = sacc[0][2];
        #pragma unroll
        for (int nt = 0; nt < 8; nt++) {
            mx0 = fmaxf(mx0, fmaxf(sacc[nt][0], sacc[nt][1]));
            mx1 = fmaxf(mx1, fmaxf(sacc[nt][2], sacc[nt][3]));
        }
        mx0 = fmaxf(mx0, __shfl_xor_sync(0xffffffffu, mx0, 1));
        mx0 = fmaxf(mx0, __shfl_xor_sync(0xffffffffu, mx0, 2));
        mx1 = fmaxf(mx1, __shfl_xor_sync(0xffffffffu, mx1, 1));
        mx1 = fmaxf(mx1, __shfl_xor_sync(0xffffffffu, mx1, 2));
        const float mn0 = fmaxf(m0, mx0);
        const float mn1 = fmaxf(m1, mx1);

        uint32_t ph[4][4];
        float s0 = 0.f, s1 = 0.f;
        #pragma unroll
        for (int nt = 0; nt < 8; nt++) {
            const float p0 = exp2_fast(sacc[nt][0] - mn0);
            const float p1 = exp2_fast(sacc[nt][1] - mn0);
            const float p2 = exp2_fast(sacc[nt][2] - mn1);
            const float p3 = exp2_fast(sacc[nt][3] - mn1);
            s0 += p0 + p1;
            s1 += p2 + p3;
            const __half2 h01 = __floats2half2_rn(p0, p1);
            const __half2 h23 = __floats2half2_rn(p2, p3);
            const int kk = nt >> 1, base = (nt & 1) * 2;
            ph[kk][base]     = h2u(h01);
            ph[kk][base + 1] = h2u(h23);
        }
        s0 += __shfl_xor_sync(0xffffffffu, s0, 1);
        s0 += __shfl_xor_sync(0xffffffffu, s0, 2);
        s1 += __shfl_xor_sync(0xffffffffu, s1, 1);
        s1 += __shfl_xor_sync(0xffffffffu, s1, 2);
        const float f0 = exp2_fast(m0 - mn0);
        const float f1 = exp2_fast(m1 - mn1);
        ls0 = ls0 * f0 + s0;
        ls1 = ls1 * f1 + s1;
        m0 = mn0; m1 = mn1;

        #pragma unroll
        for (int nt = 0; nt < 16; nt++) {
            O[nt][0] *= f0; O[nt][1] *= f0;
            O[nt][2] *= f1; O[nt][3] *= f1;
        }

        // ---- PV: warp tile 16x128, P (16x64) from registers -----------------
        const uint32_t sV = stg + 16384;
        #pragma unroll
        for (int kk = 0; kk < 4; kk++) {
            #pragma unroll
            for (int np = 0; np < 8; np++) {
                uint32_t vb[4];
                const int mat = l >> 3, idx = l & 7;
                const int key = kk * 16 + ((mat & 1) << 3) + idx;
                const int cu = np * 2 + (mat >> 1);
                ldsm_x4_t(vb, sV + SWZ(key, cu));
                mma16816h(O[np * 2 + 0], ph[kk], &vb[0]);
                mma16816h(O[np * 2 + 1], ph[kk], &vb[2]);
            }
        }
    }

    // ---- epilogue: normalize, write GEMM2's A (fp16) ----------------------
    const float inv0 = 1.f / ls0;
    const float inv1 = 1.f / ls1;
    const int row0 = qt * ATQ + w * 16 + (l >> 2);
    const size_t s0o = (size_t)(b * S_LEN + row0) * EMB + h * DH;
    #pragma unroll
    for (int nt = 0; nt < 16; nt++) {
        const int col = nt * 8 + ((l & 3) << 1);
        const __half2 h0 = __floats2half2_rn(O[nt][0] * inv0, O[nt][1] * inv0);
        const __half2 h1 = __floats2half2_rn(O[nt][2] * inv1, O[nt][3] * inv1);
        *(__half2*)(outA + s0o + col) = h0;
        *(__half2*)(outA + s0o + (size_t)8 * EMB + col) = h1;
    }
}

// ---------------------------------------------------------------------------
extern "C" void kernel_launch(void* const* d_in, const int* in_sizes, int n_in,
                              void* d_out, int out_size)
{
    (void)in_sizes; (void)n_in; (void)out_size;
    const float* x    = (const float*)d_in[0];
    const float* Wqkv = (const float*)d_in[1];
    const float* bqkv = (const float*)d_in[2];
    const float* Wout = (const float*)d_in[3];
    const float* bout = (const float*)d_in[4];
    float* out = (float*)d_out;

    __half *a16, *wq, *wo, *q16, *k16, *v16;
    cudaGetSymbolAddress((void**)&a16, g_a16);
    cudaGetSymbolAddress((void**)&wq, g_wq);
    cudaGetSymbolAddress((void**)&wo, g_wo);
    cudaGetSymbolAddress((void**)&q16, g_q16);
    cudaGetSymbolAddress((void**)&k16, g_k16);
    cudaGetSymbolAddress((void**)&v16, g_v16);

    cudaFuncSetAttribute(gemm_mma_kernel,
                         cudaFuncAttributeMaxDynamicSharedMemorySize, GEMM_SMEM);
    cudaFuncSetAttribute(gemm_qkv_kernel,
                         cudaFuncAttributeMaxDynamicSharedMemorySize, GEMM_SMEM);
    cudaFuncSetAttribute(attn_mma_kernel,
                         cudaFuncAttributeMaxDynamicSharedMemorySize, ATTN_SMEM);

    // 0) conversions (inputs only)
    to_half_kernel<<<2048, 256>>>(x, a16, MROWS * EMB);
    transpose_half_kernel<<<dim3((3 * EMB) / 32, GK / 32), dim3(32, 8)>>>(
        Wqkv, wq, GK, 3 * EMB);
    transpose_half_kernel<<<dim3(EMB / 32, GK / 32), dim3(32, 8)>>>(
        Wout, wo, GK, EMB);

    // 1) qkv projection (fp16) fused with per-head write (Q pre-scaled)
    gemm_qkv_kernel<<<dim3((3 * EMB) / 128, MROWS / 256), 256, GEMM_SMEM>>>(
        a16, wq, bqkv);

    // 2) FA2-style attention (fp16, 64-key tiles); writes GEMM2's A (fp16)
    attn_mma_kernel<<<dim3(S_LEN / ATQ, NH, BATCH), 256, ATTN_SMEM>>>(
        q16, k16, v16, a16);

    // 3) out = attn @ W_out + b_out  (fp16)
    gemm_mma_kernel<<<dim3(EMB / 128, MROWS / 256), 256, GEMM_SMEM>>>(
        EMB, a16, wo, bout, out);
}

// round 14
// speedup vs baseline: 1.0598x; 1.0598x over previous
#include <cuda_runtime.h>
#include <cuda_fp16.h>
#include <cstdint>

#define S_LEN 2048
#define EMB   2048
#define NH    16
#define DH    128
#define BATCH 2
#define MROWS (BATCH * S_LEN)   // 4096
#define GK    2048              // K for both projection GEMMs

// ---------------------------------------------------------------------------
// Device scratch (no cudaMalloc allowed)
// ---------------------------------------------------------------------------
__device__ __half g_a16[(size_t)MROWS * GK];              // A operand (x, then attn-out), fp16
__device__ __half g_wq[(size_t)(3 * EMB) * GK];           // W_qkv^T fp16 [6144,2048]
__device__ __half g_wo[(size_t)EMB * GK];                 // W_out^T fp16 [2048,2048]
// per-head Q/K/V fp16 (single-rounded), layout [B, H, S, DH]
// Q pre-scaled by log2(e)/sqrt(dh) so softmax runs in exp2 domain directly.
#define QKV_ELEMS ((size_t)BATCH * NH * S_LEN * DH)
__device__ __half g_q16[QKV_ELEMS];
__device__ __half g_k16[QKV_ELEMS];
__device__ __half g_v16[QKV_ELEMS];

// ---------------------------------------------------------------------------
// PTX helpers (plain sm_80+ instructions only)
// ---------------------------------------------------------------------------
__device__ __forceinline__ uint32_t smem_to_u32(const void* p) {
    uint32_t a;
    asm("{ .reg .u64 t; cvta.to.shared.u64 t, %1; cvt.u32.u64 %0, t; }"
        : "=r"(a) : "l"(p));
    return a;
}

__device__ __forceinline__ void cp_async16(uint32_t saddr, const void* gaddr) {
    asm volatile("cp.async.cg.shared.global [%0], [%1], 16;"
        :: "r"(saddr), "l"(gaddr) : "memory");
}
#define CP_COMMIT() asm volatile("cp.async.commit_group;" ::: "memory")
#define CP_WAIT(n)  asm volatile("cp.async.wait_group %0;" :: "n"(n) : "memory")

__device__ __forceinline__ void ldsm_x4(uint32_t* r, uint32_t addr) {
    asm volatile("ldmatrix.sync.aligned.m8n8.x4.shared.b16 {%0,%1,%2,%3}, [%4];"
        : "=r"(r[0]), "=r"(r[1]), "=r"(r[2]), "=r"(r[3]) : "r"(addr));
}
__device__ __forceinline__ void ldsm_x4_t(uint32_t* r, uint32_t addr) {
    asm volatile("ldmatrix.sync.aligned.m8n8.x4.trans.shared.b16 {%0,%1,%2,%3}, [%4];"
        : "=r"(r[0]), "=r"(r[1]), "=r"(r[2]), "=r"(r[3]) : "r"(addr));
}

// fp16 MMA (all tensor work)
__device__ __forceinline__ void mma16816h(float* d, const uint32_t* a,
                                          const uint32_t* b) {
    asm volatile(
        "mma.sync.aligned.m16n8k16.row.col.f32.f16.f16.f32 "
        "{%0,%1,%2,%3}, {%4,%5,%6,%7}, {%8,%9}, {%0,%1,%2,%3};"
        : "+f"(d[0]), "+f"(d[1]), "+f"(d[2]), "+f"(d[3])
        : "r"(a[0]), "r"(a[1]), "r"(a[2]), "r"(a[3]), "r"(b[0]), "r"(b[1]));
}

// Fast 2^t on FMA/ALU pipes only (no MUFU, no CVT). |rel err| < 3e-6.
__device__ __forceinline__ float exp2_fast(float t) {
    t = fmaxf(t, -126.0f);
    const float MAGIC = 12582912.0f;          // 2^23 + 2^22
    float z = t + MAGIC;
    int i = __float_as_int(z);
    float r = z - MAGIC;
    float f = t - r;                          // f in [-0.5, 0.5]
    float p = 1.3333558146e-3f;
    p = fmaf(p, f, 9.6181291076e-3f);
    p = fmaf(p, f, 5.5504108664e-2f);
    p = fmaf(p, f, 2.4022650696e-1f);
    p = fmaf(p, f, 6.9314718056e-1f);
    p = fmaf(p, f, 1.0f);
    int eb = (i + (127 - 0x4B400000)) << 23;
    return p * __int_as_float(eb);
}

__device__ __forceinline__ uint32_t h2u(__half2 v) {
    return *(uint32_t*)&v;
}

#define SOFTMAX_SCALE 0.12751744f     // log2(e) / sqrt(128)

// ---------------------------------------------------------------------------
// Conversion kernels
// ---------------------------------------------------------------------------
__global__ __launch_bounds__(256) void to_half_kernel(
    const float* __restrict__ in, __half* __restrict__ out, int n)
{
    int i = blockIdx.x * blockDim.x + threadIdx.x;
    int stride = gridDim.x * blockDim.x;
    for (; i < n; i += stride) out[i] = __float2half(in[i]);
}

// W[K,N] row-major -> T[N,K] fp16 (single rounding)
__global__ __launch_bounds__(256) void transpose_half_kernel(
    const float* __restrict__ W, __half* __restrict__ T, int K, int N)
{
    __shared__ float t[32][33];
    const int nb = blockIdx.x * 32;
    const int kb = blockIdx.y * 32;
    const int x = threadIdx.x, y = threadIdx.y;   // block (32,8)
    #pragma unroll
    for (int j = 0; j < 32; j += 8)
        t[y + j][x] = W[(size_t)(kb + y + j) * N + nb + x];
    __syncthreads();
    #pragma unroll
    for (int j = 0; j < 32; j += 8)
        T[(size_t)(nb + y + j) * K + kb + x] = __float2half(t[x][y + j]);
}

// ---------------------------------------------------------------------------
// fp16 HMMA mainloop (R12 geometry — empirically best: 2 CTA/SM, 98 regs):
// Block 128x128, 8 warps (2x4), warp tile 64x32, K-chunk 64, 2-stage buffer.
// ---------------------------------------------------------------------------
#define GBK   64
#define NCHUNK (GK / GBK)
#define TBYTES 16384
#define STAGE  (2 * TBYTES)          // 32 KB (A + B)
#define GEMM_SMEM (2 * STAGE)        // 64 KB

template <typename Epilogue>
__device__ __forceinline__ void gemm_mainloop(
    char* gsm,
    const __half* __restrict__ A, const __half* __restrict__ B,
    const float* __restrict__ bias, int bx, int by, Epilogue epi)
{
    const uint32_t sb = smem_to_u32(gsm);
    const int tid = threadIdx.x;
    const int w = tid >> 5, l = tid & 31;
    const int warp_m = w >> 2, warp_n = w & 3;

    const __half* srcs[2] = {
        A + (size_t)(by * 128) * GK,
        B + (size_t)(bx * 128) * GK };

    float acc[4][4][4];
    #pragma unroll
    for (int nt = 0; nt < 4; nt++) {
        const int n = bx * 128 + warp_n * 32 + nt * 8 + ((l & 3) << 1);
        const float b0 = bias[n], b1 = bias[n + 1];
        #pragma unroll
        for (int mt = 0; mt < 4; mt++) {
            acc[mt][nt][0] = b0; acc[mt][nt][1] = b1;
            acc[mt][nt][2] = b0; acc[mt][nt][3] = b1;
        }
    }

    auto load_chunk = [&](int kt) {
        const uint32_t st = sb + (kt & 1) * STAGE;
        const size_t kofs = (size_t)kt * GBK;
        #pragma unroll
        for (int a = 0; a < 2; a++) {
            const char* g = (const char*)(srcs[a] + kofs);
            #pragma unroll
            for (int j = 0; j < 4; j++) {
                const int u = tid + 256 * j;
                const int r = u >> 3;
                const int cu = u & 7;
                const uint32_t off = r * 128 + ((cu ^ (r & 7)) << 4);
                cp_async16(st + a * TBYTES + off,
                           g + (size_t)r * (GK * 2) + (cu << 4));
            }
        }
        CP_COMMIT();
    };

    load_chunk(0);

    for (int kt = 0; kt < NCHUNK; kt++) {
        if (kt + 1 < NCHUNK) { load_chunk(kt + 1); CP_WAIT(1); }
        else                 { CP_WAIT(0); }
        __syncthreads();

        const uint32_t st = sb + (kt & 1) * STAGE;
        const uint32_t sA = st, sB = st + TBYTES;

        #pragma unroll
        for (int kk = 0; kk < 4; kk++) {
            const int kb = kk * 32;

            uint32_t af[4][4];
            #pragma unroll
            for (int mt = 0; mt < 4; mt++) {
                const int row = warp_m * 64 + mt * 16 + (l & 15);
                const int bc = kb + ((l >> 4) << 4);
                const uint32_t off = row * 128 + (bc ^ ((row & 7) << 4));
                ldsm_x4(af[mt], sA + off);
            }

            uint32_t bf[2][4];
            #pragma unroll
            for (int np = 0; np < 2; np++) {
                const int g = l >> 3, idx = l & 7;
                const int row = warp_n * 32 + np * 16 + ((g >> 1) << 3) + idx;
                const int bc = kb + ((g & 1) << 4);
                const uint32_t off = row * 128 + (bc ^ ((row & 7) << 4));
                ldsm_x4(bf[np], sB + off);
            }

            #pragma unroll
            for (int mt = 0; mt < 4; mt++)
                #pragma unroll
                for (int nt = 0; nt < 4; nt++)
                    mma16816h(acc[mt][nt], af[mt], &bf[nt >> 1][(nt & 1) * 2]);
        }
        __syncthreads();
    }

    epi(acc, warp_m, warp_n, l);
}

// GEMM2: plain fp32 output C = A*B^T + bias
__global__ __launch_bounds__(256) void gemm_mma_kernel(
    int N,
    const __half* __restrict__ A, const __half* __restrict__ B,
    const float* __restrict__ bias, float* __restrict__ C)
{
    extern __shared__ char gsm[];
    const int bx = blockIdx.x, by = blockIdx.y;
    gemm_mainloop(gsm, A, B, bias, bx, by,
        [&](float acc[4][4][4], int warp_m, int warp_n, int l) {
            #pragma unroll
            for (int mt = 0; mt < 4; mt++) {
                const int m = by * 128 + warp_m * 64 + mt * 16 + (l >> 2);
                float* c0 = C + (size_t)m * N + bx * 128 + warp_n * 32 + ((l & 3) << 1);
                #pragma unroll
                for (int nt = 0; nt < 4; nt++) {
                    *(float2*)(c0 + nt * 8) =
                        make_float2(acc[mt][nt][0], acc[mt][nt][1]);
                    *(float2*)(c0 + (size_t)8 * N + nt * 8) =
                        make_float2(acc[mt][nt][2], acc[mt][nt][3]);
                }
            }
        });
}

// GEMM1 fused: writes per-head fp16 Q (pre-scaled), K, V (single-rounded).
__global__ __launch_bounds__(256) void gemm_qkv_kernel(
    const __half* __restrict__ A, const __half* __restrict__ B,
    const float* __restrict__ bias)
{
    extern __shared__ char gsm[];
    const int bx = blockIdx.x, by = blockIdx.y;
    const int region = bx % 3;        // 0=q, 1=k, 2=v
    const int head   = bx / 3;
    __half* H = (region == 0) ? g_q16 : (region == 1) ? g_k16 : g_v16;
    const float scl = (region == 0) ? SOFTMAX_SCALE : 1.0f;

    gemm_mainloop(gsm, A, B, bias, bx, by,
        [&](float acc[4][4][4], int warp_m, int warp_n, int l) {
            #pragma unroll
            for (int mt = 0; mt < 4; mt++) {
                const int m = by * 128 + warp_m * 64 + mt * 16 + (l >> 2);
                const int b = m >> 11, s = m & (S_LEN - 1);
                const size_t base =
                    (((size_t)(b * NH + head)) * S_LEN + s) * DH;
                #pragma unroll
                for (int nt = 0; nt < 4; nt++) {
                    const int d = warp_n * 32 + nt * 8 + ((l & 3) << 1);
                    const __half2 h0 = __floats2half2_rn(acc[mt][nt][0] * scl,
                                                         acc[mt][nt][1] * scl);
                    const __half2 h1 = __floats2half2_rn(acc[mt][nt][2] * scl,
                                                         acc[mt][nt][3] * scl);
                    *(__half2*)(H + base + d) = h0;
                    *(__half2*)(H + base + (size_t)8 * DH + d) = h1;
                }
            }
        });
}

// ---------------------------------------------------------------------------
// FA2-style tensor-core attention, fp16 single-term, K-tile = 64 keys
// (R13 attention — empirically best):
//   QK: Q * K (Q pre-scaled) ; PV: P * V
// 8 warps; each warp owns 16 Q rows (QK 16x64, PV 16x128).
// 3-stage KV pipeline (32 KB/stage), 1 sync per tile.
// ---------------------------------------------------------------------------
#define ATQ 128
#define AKT 64
#define ANT (S_LEN / AKT)             // 32

#define ASM_Q  0                      // 32768 bytes (128 rows x 256B)
#define ASM_KV 32768                  // 3 stages x 32768 (K 16KB | V 16KB)
#define KVSTAGE 32768
#define ATTN_SMEM (32768 + 3 * KVSTAGE)  // 131072

#define SWZ(row, cu) ((row) * 256 + ((((cu) ^ ((row) & 7))) << 4))

__global__ __launch_bounds__(256) void attn_mma_kernel(
    const __half* __restrict__ q16, const __half* __restrict__ k16,
    const __half* __restrict__ v16,
    __half* __restrict__ outA)
{
    extern __shared__ char gsm[];
    const uint32_t sb = smem_to_u32(gsm);
    const int tid = threadIdx.x;
    const int w = tid >> 5, l = tid & 31;
    const int qt = blockIdx.x, h = blockIdx.y, b = blockIdx.z;

    const size_t head = ((size_t)(b * NH + h)) * S_LEN * DH;
    const __half* Q_g = q16 + head + (size_t)qt * ATQ * DH;

    auto load_kv = [&](int t) {
        const uint32_t st = sb + ASM_KV + (t % 3) * KVSTAGE;
        const size_t base = head + (size_t)t * AKT * DH;
        const __half* srcs[2] = {k16 + base, v16 + base};
        #pragma unroll
        for (int a = 0; a < 2; a++) {
            #pragma unroll
            for (int j = 0; j < 4; j++) {       // 64 rows x 16 units = 1024
                const int u = tid + 256 * j;
                const int row = u >> 4, cu = u & 15;
                cp_async16(st + a * 16384 + SWZ(row, cu),
                           (const char*)srcs[a] + (size_t)row * 256 + cu * 16);
            }
        }
        CP_COMMIT();
    };

    // Q loads committed together with KV(0) as group 0.
    #pragma unroll
    for (int j = 0; j < 8; j++) {
        const int u = tid + 256 * j;
        const int row = u >> 4, cu = u & 15;
        cp_async16(sb + ASM_Q + SWZ(row, cu),
                   (const char*)Q_g + (size_t)row * 256 + cu * 16);
    }
    load_kv(0);
    load_kv(1);

    // Wait for group 0 (Q + KV0), then cache ALL Q fragments in registers.
    CP_WAIT(1);
    __syncthreads();
    uint32_t qf[8][4];
    #pragma unroll
    for (int kk = 0; kk < 8; kk++) {
        const int row = w * 16 + (l & 15);
        const int cu = kk * 2 + (l >> 4);
        ldsm_x4(qf[kk], sb + ASM_Q + SWZ(row, cu));
    }

    float m0 = -1e9f, m1 = -1e9f, ls0 = 0.f, ls1 = 0.f;
    float O[16][4];
    #pragma unroll
    for (int nt = 0; nt < 16; nt++)
        #pragma unroll
        for (int c = 0; c < 4; c++) O[nt][c] = 0.f;

    for (int t = 0; t < ANT; t++) {
        if (t > 0) {
            if (t + 1 < ANT) { CP_WAIT(1); } else { CP_WAIT(0); }
            __syncthreads();
        }
        if (t + 2 < ANT) load_kv(t + 2);

        const uint32_t stg = sb + ASM_KV + (t % 3) * KVSTAGE;

        // ---- QK: sacc[8][4], warp tile 16x64, Q from registers -------------
        float sacc[8][4];
        #pragma unroll
        for (int nt = 0; nt < 8; nt++)
            #pragma unroll
            for (int c = 0; c < 4; c++) sacc[nt][c] = 0.f;

        #pragma unroll
        for (int kk = 0; kk < 8; kk++) {
            uint32_t kf[4][4];
            #pragma unroll
            for (int np = 0; np < 4; np++) {
                const int g = l >> 3, idx = l & 7;
                const int krow = np * 16 + ((g >> 1) << 3) + idx;
                const int bcu = kk * 2 + (g & 1);
                ldsm_x4(kf[np], stg + SWZ(krow, bcu));
            }
            #pragma unroll
            for (int nt = 0; nt < 8; nt++)
                mma16816h(sacc[nt], qf[kk], &kf[nt >> 1][(nt & 1) * 2]);
        }

        // ---- softmax in registers (scores already in exp2 domain) ----------
        float mx0 = sacc[0][0], mx1 = sacc[0][2];
        #pragma unroll
        for (int nt = 0; nt < 8; nt++) {
            mx0 = fmaxf(mx0, fmaxf(sacc[nt][0], sacc[nt][1]));
            mx1 = fmaxf(mx1, fmaxf(sacc[nt][2], sacc[nt][3]));
        }
        mx0 = fmaxf(mx0, __shfl_xor_sync(0xffffffffu, mx0, 1));
        mx0 = fmaxf(mx0, __shfl_xor_sync(0xffffffffu, mx0, 2));
        mx1 = fmaxf(mx1, __shfl_xor_sync(0xffffffffu, mx1, 1));
        mx1 = fmaxf(mx1, __shfl_xor_sync(0xffffffffu, mx1, 2));
        const float mn0 = fmaxf(m0, mx0);
        const float mn1 = fmaxf(m1, mx1);

        uint32_t ph[4][4];
        float s0 = 0.f, s1 = 0.f;
        #pragma unroll
        for (int nt = 0; nt < 8; nt++) {
            const float p0 = exp2_fast(sacc[nt][0] - mn0);
            const float p1 = exp2_fast(sacc[nt][1] - mn0);
            const float p2 = exp2_fast(sacc[nt][2] - mn1);
            const float p3 = exp2_fast(sacc[nt][3] - mn1);
            s0 += p0 + p1;
            s1 += p2 + p3;
            const __half2 h01 = __floats2half2_rn(p0, p1);
            const __half2 h23 = __floats2half2_rn(p2, p3);
            const int kk = nt >> 1, base = (nt & 1) * 2;
            ph[kk][base]     = h2u(h01);
            ph[kk][base + 1] = h2u(h23);
        }
        s0 += __shfl_xor_sync(0xffffffffu, s0, 1);
        s0 += __shfl_xor_sync(0xffffffffu, s0, 2);
        s1 += __shfl_xor_sync(0xffffffffu, s1, 1);
        s1 += __shfl_xor_sync(0xffffffffu, s1, 2);
        const float f0 = exp2_fast(m0 - mn0);
        const float f1 = exp2_fast(m1 - mn1);
        ls0 = ls0 * f0 + s0;
        ls1 = ls1 * f1 + s1;
        m0 = mn0; m1 = mn1;

        #pragma unroll
        for (int nt = 0; nt < 16; nt++) {
            O[nt][0] *= f0; O[nt][1] *= f0;
            O[nt][2] *= f1; O[nt][3] *= f1;
        }

        // ---- PV: warp tile 16x128, P (16x64) from registers -----------------
        const uint32_t sV = stg + 16384;
        #pragma unroll
        for (int kk = 0; kk < 4; kk++) {
            #pragma unroll
            for (int np = 0; np < 8; np++) {
                uint32_t vb[4];
                const int mat = l >> 3, idx = l & 7;
                const int key = kk * 16 + ((mat & 1) << 3) + idx;
                const int cu = np * 2 + (mat >> 1);
                ldsm_x4_t(vb, sV + SWZ(key, cu));
                mma16816h(O[np * 2 + 0], ph[kk], &vb[0]);
                mma16816h(O[np * 2 + 1], ph[kk], &vb[2]);
            }
        }
    }

    // ---- epilogue: normalize, write GEMM2's A (fp16) ----------------------
    const float inv0 = 1.f / ls0;
    const float inv1 = 1.f / ls1;
    const int row0 = qt * ATQ + w * 16 + (l >> 2);
    const size_t s0o = (size_t)(b * S_LEN + row0) * EMB + h * DH;
    #pragma unroll
    for (int nt = 0; nt < 16; nt++) {
        const int col = nt * 8 + ((l & 3) << 1);
        const __half2 h0 = __floats2half2_rn(O[nt][0] * inv0, O[nt][1] * inv0);
        const __half2 h1 = __floats2half2_rn(O[nt][2] * inv1, O[nt][3] * inv1);
        *(__half2*)(outA + s0o + col) = h0;
        *(__half2*)(outA + s0o + (size_t)8 * EMB + col) = h1;
    }
}

// ---------------------------------------------------------------------------
extern "C" void kernel_launch(void* const* d_in, const int* in_sizes, int n_in,
                              void* d_out, int out_size)
{
    (void)in_sizes; (void)n_in; (void)out_size;
    const float* x    = (const float*)d_in[0];
    const float* Wqkv = (const float*)d_in[1];
    const float* bqkv = (const float*)d_in[2];
    const float* Wout = (const float*)d_in[3];
    const float* bout = (const float*)d_in[4];
    float* out = (float*)d_out;

    __half *a16, *wq, *wo, *q16, *k16, *v16;
    cudaGetSymbolAddress((void**)&a16, g_a16);
    cudaGetSymbolAddress((void**)&wq, g_wq);
    cudaGetSymbolAddress((void**)&wo, g_wo);
    cudaGetSymbolAddress((void**)&q16, g_q16);
    cudaGetSymbolAddress((void**)&k16, g_k16);
    cudaGetSymbolAddress((void**)&v16, g_v16);

    cudaFuncSetAttribute(gemm_mma_kernel,
                         cudaFuncAttributeMaxDynamicSharedMemorySize, GEMM_SMEM);
    cudaFuncSetAttribute(gemm_qkv_kernel,
                         cudaFuncAttributeMaxDynamicSharedMemorySize, GEMM_SMEM);
    cudaFuncSetAttribute(attn_mma_kernel,
                         cudaFuncAttributeMaxDynamicSharedMemorySize, ATTN_SMEM);

    // 0) conversions (inputs only)
    to_half_kernel<<<2048, 256>>>(x, a16, MROWS * EMB);
    transpose_half_kernel<<<dim3((3 * EMB) / 32, GK / 32), dim3(32, 8)>>>(
        Wqkv, wq, GK, 3 * EMB);
    transpose_half_kernel<<<dim3(EMB / 32, GK / 32), dim3(32, 8)>>>(
        Wout, wo, GK, EMB);

    // 1) qkv projection (fp16) fused with per-head write (Q pre-scaled)
    gemm_qkv_kernel<<<dim3((3 * EMB) / 128, MROWS / 128), 256, GEMM_SMEM>>>(
        a16, wq, bqkv);

    // 2) FA2-style attention (fp16, 64-key tiles); writes GEMM2's A (fp16)
    attn_mma_kernel<<<dim3(S_LEN / ATQ, NH, BATCH), 256, ATTN_SMEM>>>(
        q16, k16, v16, a16);

    // 3) out = attn @ W_out + b_out  (fp16)
    gemm_mma_kernel<<<dim3(EMB / 128, MROWS / 128), 256, GEMM_SMEM>>>(
        EMB, a16, wo, bout, out);
}

// round 15
// speedup vs baseline: 1.1891x; 1.1221x over previous
#include <cuda_runtime.h>
#include <cuda_fp16.h>
#include <cstdint>

#define S_LEN 2048
#define EMB   2048
#define NH    16
#define DH    128
#define BATCH 2
#define MROWS (BATCH * S_LEN)   // 4096
#define GK    2048              // K for both projection GEMMs

// ---------------------------------------------------------------------------
// Device scratch (no cudaMalloc allowed)
// ---------------------------------------------------------------------------
__device__ __half g_a16[(size_t)MROWS * GK];              // A operand (x, then attn-out), fp16
__device__ __half g_wq[(size_t)(3 * EMB) * GK];           // W_qkv^T fp16 [6144,2048]
__device__ __half g_wo[(size_t)EMB * GK];                 // W_out^T fp16 [2048,2048]
// per-head Q/K/V fp16 (single-rounded), layout [B, H, S, DH]
// Q pre-scaled by log2(e)/sqrt(dh) so softmax runs in exp2 domain directly.
#define QKV_ELEMS ((size_t)BATCH * NH * S_LEN * DH)
__device__ __half g_q16[QKV_ELEMS];
__device__ __half g_k16[QKV_ELEMS];
__device__ __half g_v16[QKV_ELEMS];

// ---------------------------------------------------------------------------
// PTX helpers (plain sm_80+ instructions only)
// ---------------------------------------------------------------------------
__device__ __forceinline__ uint32_t smem_to_u32(const void* p) {
    uint32_t a;
    asm("{ .reg .u64 t; cvta.to.shared.u64 t, %1; cvt.u32.u64 %0, t; }"
        : "=r"(a) : "l"(p));
    return a;
}

__device__ __forceinline__ void cp_async16(uint32_t saddr, const void* gaddr) {
    asm volatile("cp.async.cg.shared.global [%0], [%1], 16;"
        :: "r"(saddr), "l"(gaddr) : "memory");
}
#define CP_COMMIT() asm volatile("cp.async.commit_group;" ::: "memory")
#define CP_WAIT(n)  asm volatile("cp.async.wait_group %0;" :: "n"(n) : "memory")

__device__ __forceinline__ void ldsm_x4(uint32_t* r, uint32_t addr) {
    asm volatile("ldmatrix.sync.aligned.m8n8.x4.shared.b16 {%0,%1,%2,%3}, [%4];"
        : "=r"(r[0]), "=r"(r[1]), "=r"(r[2]), "=r"(r[3]) : "r"(addr));
}
__device__ __forceinline__ void ldsm_x4_t(uint32_t* r, uint32_t addr) {
    asm volatile("ldmatrix.sync.aligned.m8n8.x4.trans.shared.b16 {%0,%1,%2,%3}, [%4];"
        : "=r"(r[0]), "=r"(r[1]), "=r"(r[2]), "=r"(r[3]) : "r"(addr));
}

// fp16 MMA (all tensor work)
__device__ __forceinline__ void mma16816h(float* d, const uint32_t* a,
                                          const uint32_t* b) {
    asm volatile(
        "mma.sync.aligned.m16n8k16.row.col.f32.f16.f16.f32 "
        "{%0,%1,%2,%3}, {%4,%5,%6,%7}, {%8,%9}, {%0,%1,%2,%3};"
        : "+f"(d[0]), "+f"(d[1]), "+f"(d[2]), "+f"(d[3])
        : "r"(a[0]), "r"(a[1]), "r"(a[2]), "r"(a[3]), "r"(b[0]), "r"(b[1]));
}

// Fast 2^t on FMA/ALU pipes only (no MUFU, no CVT). |rel err| < 3e-6.
__device__ __forceinline__ float exp2_fast(float t) {
    t = fmaxf(t, -126.0f);
    const float MAGIC = 12582912.0f;          // 2^23 + 2^22
    float z = t + MAGIC;
    int i = __float_as_int(z);
    float r = z - MAGIC;
    float f = t - r;                          // f in [-0.5, 0.5]
    float p = 1.3333558146e-3f;
    p = fmaf(p, f, 9.6181291076e-3f);
    p = fmaf(p, f, 5.5504108664e-2f);
    p = fmaf(p, f, 2.4022650696e-1f);
    p = fmaf(p, f, 6.9314718056e-1f);
    p = fmaf(p, f, 1.0f);
    int eb = (i + (127 - 0x4B400000)) << 23;
    return p * __int_as_float(eb);
}

__device__ __forceinline__ uint32_t h2u(__half2 v) {
    return *(uint32_t*)&v;
}

#define SOFTMAX_SCALE 0.12751744f     // log2(e) / sqrt(128)

// ---------------------------------------------------------------------------
// Conversion kernels
// ---------------------------------------------------------------------------
__global__ __launch_bounds__(256) void to_half_kernel(
    const float* __restrict__ in, __half* __restrict__ out, int n)
{
    int i = blockIdx.x * blockDim.x + threadIdx.x;
    int stride = gridDim.x * blockDim.x;
    for (; i < n; i += stride) out[i] = __float2half(in[i]);
}

// W[K,N] row-major -> T[N,K] fp16 (single rounding)
__global__ __launch_bounds__(256) void transpose_half_kernel(
    const float* __restrict__ W, __half* __restrict__ T, int K, int N)
{
    __shared__ float t[32][33];
    const int nb = blockIdx.x * 32;
    const int kb = blockIdx.y * 32;
    const int x = threadIdx.x, y = threadIdx.y;   // block (32,8)
    #pragma unroll
    for (int j = 0; j < 32; j += 8)
        t[y + j][x] = W[(size_t)(kb + y + j) * N + nb + x];
    __syncthreads();
    #pragma unroll
    for (int j = 0; j < 32; j += 8)
        T[(size_t)(nb + y + j) * K + kb + x] = __float2half(t[x][y + j]);
}

// ---------------------------------------------------------------------------
// fp16 HMMA mainloop (R12 geometry — empirically best: 2 CTA/SM, 98 regs):
// Block 128x128, 8 warps (2x4), warp tile 64x32, K-chunk 64, 2-stage buffer.
// ---------------------------------------------------------------------------
#define GBK   64
#define NCHUNK (GK / GBK)
#define TBYTES 16384
#define STAGE  (2 * TBYTES)          // 32 KB (A + B)
#define GEMM_SMEM (2 * STAGE)        // 64 KB

template <typename Epilogue>
__device__ __forceinline__ void gemm_mainloop(
    char* gsm,
    const __half* __restrict__ A, const __half* __restrict__ B,
    const float* __restrict__ bias, int bx, int by, Epilogue epi)
{
    const uint32_t sb = smem_to_u32(gsm);
    const int tid = threadIdx.x;
    const int w = tid >> 5, l = tid & 31;
    const int warp_m = w >> 2, warp_n = w & 3;

    const __half* srcs[2] = {
        A + (size_t)(by * 128) * GK,
        B + (size_t)(bx * 128) * GK };

    float acc[4][4][4];
    #pragma unroll
    for (int nt = 0; nt < 4; nt++) {
        const int n = bx * 128 + warp_n * 32 + nt * 8 + ((l & 3) << 1);
        const float b0 = bias[n], b1 = bias[n + 1];
        #pragma unroll
        for (int mt = 0; mt < 4; mt++) {
            acc[mt][nt][0] = b0; acc[mt][nt][1] = b1;
            acc[mt][nt][2] = b0; acc[mt][nt][3] = b1;
        }
    }

    auto load_chunk = [&](int kt) {
        const uint32_t st = sb + (kt & 1) * STAGE;
        const size_t kofs = (size_t)kt * GBK;
        #pragma unroll
        for (int a = 0; a < 2; a++) {
            const char* g = (const char*)(srcs[a] + kofs);
            #pragma unroll
            for (int j = 0; j < 4; j++) {
                const int u = tid + 256 * j;
                const int r = u >> 3;
                const int cu = u & 7;
                const uint32_t off = r * 128 + ((cu ^ (r & 7)) << 4);
                cp_async16(st + a * TBYTES + off,
                           g + (size_t)r * (GK * 2) + (cu << 4));
            }
        }
        CP_COMMIT();
    };

    load_chunk(0);

    for (int kt = 0; kt < NCHUNK; kt++) {
        if (kt + 1 < NCHUNK) { load_chunk(kt + 1); CP_WAIT(1); }
        else                 { CP_WAIT(0); }
        __syncthreads();

        const uint32_t st = sb + (kt & 1) * STAGE;
        const uint32_t sA = st, sB = st + TBYTES;

        #pragma unroll
        for (int kk = 0; kk < 4; kk++) {
            const int kb = kk * 32;

            uint32_t af[4][4];
            #pragma unroll
            for (int mt = 0; mt < 4; mt++) {
                const int row = warp_m * 64 + mt * 16 + (l & 15);
                const int bc = kb + ((l >> 4) << 4);
                const uint32_t off = row * 128 + (bc ^ ((row & 7) << 4));
                ldsm_x4(af[mt], sA + off);
            }

            uint32_t bf[2][4];
            #pragma unroll
            for (int np = 0; np < 2; np++) {
                const int g = l >> 3, idx = l & 7;
                const int row = warp_n * 32 + np * 16 + ((g >> 1) << 3) + idx;
                const int bc = kb + ((g & 1) << 4);
                const uint32_t off = row * 128 + (bc ^ ((row & 7) << 4));
                ldsm_x4(bf[np], sB + off);
            }

            #pragma unroll
            for (int mt = 0; mt < 4; mt++)
                #pragma unroll
                for (int nt = 0; nt < 4; nt++)
                    mma16816h(acc[mt][nt], af[mt], &bf[nt >> 1][(nt & 1) * 2]);
        }
        __syncthreads();
    }

    epi(acc, warp_m, warp_n, l);
}

// GEMM2: plain fp32 output C = A*B^T + bias
__global__ __launch_bounds__(256) void gemm_mma_kernel(
    int N,
    const __half* __restrict__ A, const __half* __restrict__ B,
    const float* __restrict__ bias, float* __restrict__ C)
{
    extern __shared__ char gsm[];
    const int bx = blockIdx.x, by = blockIdx.y;
    gemm_mainloop(gsm, A, B, bias, bx, by,
        [&](float acc[4][4][4], int warp_m, int warp_n, int l) {
            #pragma unroll
            for (int mt = 0; mt < 4; mt++) {
                const int m = by * 128 + warp_m * 64 + mt * 16 + (l >> 2);
                float* c0 = C + (size_t)m * N + bx * 128 + warp_n * 32 + ((l & 3) << 1);
                #pragma unroll
                for (int nt = 0; nt < 4; nt++) {
                    *(float2*)(c0 + nt * 8) =
                        make_float2(acc[mt][nt][0], acc[mt][nt][1]);
                    *(float2*)(c0 + (size_t)8 * N + nt * 8) =
                        make_float2(acc[mt][nt][2], acc[mt][nt][3]);
                }
            }
        });
}

// GEMM1 fused: writes per-head fp16 Q (pre-scaled), K, V (single-rounded).
__global__ __launch_bounds__(256) void gemm_qkv_kernel(
    const __half* __restrict__ A, const __half* __restrict__ B,
    const float* __restrict__ bias)
{
    extern __shared__ char gsm[];
    const int bx = blockIdx.x, by = blockIdx.y;
    const int region = bx % 3;        // 0=q, 1=k, 2=v
    const int head   = bx / 3;
    __half* H = (region == 0) ? g_q16 : (region == 1) ? g_k16 : g_v16;
    const float scl = (region == 0) ? SOFTMAX_SCALE : 1.0f;

    gemm_mainloop(gsm, A, B, bias, bx, by,
        [&](float acc[4][4][4], int warp_m, int warp_n, int l) {
            #pragma unroll
            for (int mt = 0; mt < 4; mt++) {
                const int m = by * 128 + warp_m * 64 + mt * 16 + (l >> 2);
                const int b = m >> 11, s = m & (S_LEN - 1);
                const size_t base =
                    (((size_t)(b * NH + head)) * S_LEN + s) * DH;
                #pragma unroll
                for (int nt = 0; nt < 4; nt++) {
                    const int d = warp_n * 32 + nt * 8 + ((l & 3) << 1);
                    const __half2 h0 = __floats2half2_rn(acc[mt][nt][0] * scl,
                                                         acc[mt][nt][1] * scl);
                    const __half2 h1 = __floats2half2_rn(acc[mt][nt][2] * scl,
                                                         acc[mt][nt][3] * scl);
                    *(__half2*)(H + base + d) = h0;
                    *(__half2*)(H + base + (size_t)8 * DH + d) = h1;
                }
            }
        });
}

// ---------------------------------------------------------------------------
// FA2-style tensor-core attention, fp16 single-term, K-tile = 64 keys.
// NEW: Q-tile 64 rows, 4 warps (128 threads), smem 112 KB -> 2 CTAs/SM so
// softmax of one CTA overlaps HMMA of the other.
//   QK: Q * K (Q pre-scaled) ; PV: P * V
// Each warp owns 16 Q rows (QK 16x64, PV 16x128). 3-stage KV pipeline.
// ---------------------------------------------------------------------------
#define ATQ 64
#define AKT 64
#define ANT (S_LEN / AKT)             // 32

#define ASM_Q  0                      // 16384 bytes (64 rows x 256B)
#define ASM_KV 16384                  // 3 stages x 32768 (K 16KB | V 16KB)
#define KVSTAGE 32768
#define ATTN_SMEM (16384 + 3 * KVSTAGE)  // 114688 (112 KB)

#define SWZ(row, cu) ((row) * 256 + ((((cu) ^ ((row) & 7))) << 4))

__global__ __launch_bounds__(128, 2) void attn_mma_kernel(
    const __half* __restrict__ q16, const __half* __restrict__ k16,
    const __half* __restrict__ v16,
    __half* __restrict__ outA)
{
    extern __shared__ char gsm[];
    const uint32_t sb = smem_to_u32(gsm);
    const int tid = threadIdx.x;
    const int w = tid >> 5, l = tid & 31;
    const int qt = blockIdx.x, h = blockIdx.y, b = blockIdx.z;

    const size_t head = ((size_t)(b * NH + h)) * S_LEN * DH;
    const __half* Q_g = q16 + head + (size_t)qt * ATQ * DH;

    auto load_kv = [&](int t) {
        const uint32_t st = sb + ASM_KV + (t % 3) * KVSTAGE;
        const size_t base = head + (size_t)t * AKT * DH;
        const __half* srcs[2] = {k16 + base, v16 + base};
        #pragma unroll
        for (int a = 0; a < 2; a++) {
            #pragma unroll
            for (int j = 0; j < 8; j++) {       // 64 rows x 16 units = 1024
                const int u = tid + 128 * j;
                const int row = u >> 4, cu = u & 15;
                cp_async16(st + a * 16384 + SWZ(row, cu),
                           (const char*)srcs[a] + (size_t)row * 256 + cu * 16);
            }
        }
        CP_COMMIT();
    };

    // Q loads committed together with KV(0) as group 0.
    #pragma unroll
    for (int j = 0; j < 8; j++) {                // 64 rows x 16 units = 1024
        const int u = tid + 128 * j;
        const int row = u >> 4, cu = u & 15;
        cp_async16(sb + ASM_Q + SWZ(row, cu),
                   (const char*)Q_g + (size_t)row * 256 + cu * 16);
    }
    load_kv(0);
    load_kv(1);

    // Wait for group 0 (Q + KV0), then cache ALL Q fragments in registers.
    CP_WAIT(1);
    __syncthreads();
    uint32_t qf[8][4];
    #pragma unroll
    for (int kk = 0; kk < 8; kk++) {
        const int row = w * 16 + (l & 15);
        const int cu = kk * 2 + (l >> 4);
        ldsm_x4(qf[kk], sb + ASM_Q + SWZ(row, cu));
    }

    float m0 = -1e9f, m1 = -1e9f, ls0 = 0.f, ls1 = 0.f;
    float O[16][4];
    #pragma unroll
    for (int nt = 0; nt < 16; nt++)
        #pragma unroll
        for (int c = 0; c < 4; c++) O[nt][c] = 0.f;

    for (int t = 0; t < ANT; t++) {
        if (t > 0) {
            if (t + 1 < ANT) { CP_WAIT(1); } else { CP_WAIT(0); }
            __syncthreads();
        }
        if (t + 2 < ANT) load_kv(t + 2);

        const uint32_t stg = sb + ASM_KV + (t % 3) * KVSTAGE;

        // ---- QK: sacc[8][4], warp tile 16x64, Q from registers -------------
        float sacc[8][4];
        #pragma unroll
        for (int nt = 0; nt < 8; nt++)
            #pragma unroll
            for (int c = 0; c < 4; c++) sacc[nt][c] = 0.f;

        #pragma unroll
        for (int kk = 0; kk < 8; kk++) {
            uint32_t kf[4][4];
            #pragma unroll
            for (int np = 0; np < 4; np++) {
                const int g = l >> 3, idx = l & 7;
                const int krow = np * 16 + ((g >> 1) << 3) + idx;
                const int bcu = kk * 2 + (g & 1);
                ldsm_x4(kf[np], stg + SWZ(krow, bcu));
            }
            #pragma unroll
            for (int nt = 0; nt < 8; nt++)
                mma16816h(sacc[nt], qf[kk], &kf[nt >> 1][(nt & 1) * 2]);
        }

        // ---- softmax in registers (scores already in exp2 domain) ----------
        float mx0 = sacc[0][0], mx1 = sacc[0][2];
        #pragma unroll
        for (int nt = 0; nt < 8; nt++) {
            mx0 = fmaxf(mx0, fmaxf(sacc[nt][0], sacc[nt][1]));
            mx1 = fmaxf(mx1, fmaxf(sacc[nt][2], sacc[nt][3]));
        }
        mx0 = fmaxf(mx0, __shfl_xor_sync(0xffffffffu, mx0, 1));
        mx0 = fmaxf(mx0, __shfl_xor_sync(0xffffffffu, mx0, 2));
        mx1 = fmaxf(mx1, __shfl_xor_sync(0xffffffffu, mx1, 1));
        mx1 = fmaxf(mx1, __shfl_xor_sync(0xffffffffu, mx1, 2));
        const float mn0 = fmaxf(m0, mx0);
        const float mn1 = fmaxf(m1, mx1);

        uint32_t ph[4][4];
        float s0 = 0.f, s1 = 0.f;
        #pragma unroll
        for (int nt = 0; nt < 8; nt++) {
            const float p0 = exp2_fast(sacc[nt][0] - mn0);
            const float p1 = exp2_fast(sacc[nt][1] - mn0);
            const float p2 = exp2_fast(sacc[nt][2] - mn1);
            const float p3 = exp2_fast(sacc[nt][3] - mn1);
            s0 += p0 + p1;
            s1 += p2 + p3;
            const __half2 h01 = __floats2half2_rn(p0, p1);
            const __half2 h23 = __floats2half2_rn(p2, p3);
            const int kk = nt >> 1, base = (nt & 1) * 2;
            ph[kk][base]     = h2u(h01);
            ph[kk][base + 1] = h2u(h23);
        }
        s0 += __shfl_xor_sync(0xffffffffu, s0, 1);
        s0 += __shfl_xor_sync(0xffffffffu, s0, 2);
        s1 += __shfl_xor_sync(0xffffffffu, s1, 1);
        s1 += __shfl_xor_sync(0xffffffffu, s1, 2);
        const float f0 = exp2_fast(m0 - mn0);
        const float f1 = exp2_fast(m1 - mn1);
        ls0 = ls0 * f0 + s0;
        ls1 = ls1 * f1 + s1;
        m0 = mn0; m1 = mn1;

        #pragma unroll
        for (int nt = 0; nt < 16; nt++) {
            O[nt][0] *= f0; O[nt][1] *= f0;
            O[nt][2] *= f1; O[nt][3] *= f1;
        }

        // ---- PV: warp tile 16x128, P (16x64) from registers -----------------
        const uint32_t sV = stg + 16384;
        #pragma unroll
        for (int kk = 0; kk < 4; kk++) {
            #pragma unroll
            for (int np = 0; np < 8; np++) {
                uint32_t vb[4];
                const int mat = l >> 3, idx = l & 7;
                const int key = kk * 16 + ((mat & 1) << 3) + idx;
                const int cu = np * 2 + (mat >> 1);
                ldsm_x4_t(vb, sV + SWZ(key, cu));
                mma16816h(O[np * 2 + 0], ph[kk], &vb[0]);
                mma16816h(O[np * 2 + 1], ph[kk], &vb[2]);
            }
        }
    }

    // ---- epilogue: normalize, write GEMM2's A (fp16) ----------------------
    const float inv0 = 1.f / ls0;
    const float inv1 = 1.f / ls1;
    const int row0 = qt * ATQ + w * 16 + (l >> 2);
    const size_t s0o = (size_t)(b * S_LEN + row0) * EMB + h * DH;
    #pragma unroll
    for (int nt = 0; nt < 16; nt++) {
        const int col = nt * 8 + ((l & 3) << 1);
        const __half2 h0 = __floats2half2_rn(O[nt][0] * inv0, O[nt][1] * inv0);
        const __half2 h1 = __floats2half2_rn(O[nt][2] * inv1, O[nt][3] * inv1);
        *(__half2*)(outA + s0o + col) = h0;
        *(__half2*)(outA + s0o + (size_t)8 * EMB + col) = h1;
    }
}

// ---------------------------------------------------------------------------
extern "C" void kernel_launch(void* const* d_in, const int* in_sizes, int n_in,
                              void* d_out, int out_size)
{
    (void)in_sizes; (void)n_in; (void)out_size;
    const float* x    = (const float*)d_in[0];
    const float* Wqkv = (const float*)d_in[1];
    const float* bqkv = (const float*)d_in[2];
    const float* Wout = (const float*)d_in[3];
    const float* bout = (const float*)d_in[4];
    float* out = (float*)d_out;

    __half *a16, *wq, *wo, *q16, *k16, *v16;
    cudaGetSymbolAddress((void**)&a16, g_a16);
    cudaGetSymbolAddress((void**)&wq, g_wq);
    cudaGetSymbolAddress((void**)&wo, g_wo);
    cudaGetSymbolAddress((void**)&q16, g_q16);
    cudaGetSymbolAddress((void**)&k16, g_k16);
    cudaGetSymbolAddress((void**)&v16, g_v16);

    cudaFuncSetAttribute(gemm_mma_kernel,
                         cudaFuncAttributeMaxDynamicSharedMemorySize, GEMM_SMEM);
    cudaFuncSetAttribute(gemm_qkv_kernel,
                         cudaFuncAttributeMaxDynamicSharedMemorySize, GEMM_SMEM);
    cudaFuncSetAttribute(attn_mma_kernel,
                         cudaFuncAttributeMaxDynamicSharedMemorySize, ATTN_SMEM);

    // 0) conversions (inputs only)
    to_half_kernel<<<2048, 256>>>(x, a16, MROWS * EMB);
    transpose_half_kernel<<<dim3((3 * EMB) / 32, GK / 32), dim3(32, 8)>>>(
        Wqkv, wq, GK, 3 * EMB);
    transpose_half_kernel<<<dim3(EMB / 32, GK / 32), dim3(32, 8)>>>(
        Wout, wo, GK, EMB);

    // 1) qkv projection (fp16) fused with per-head write (Q pre-scaled)
    gemm_qkv_kernel<<<dim3((3 * EMB) / 128, MROWS / 128), 256, GEMM_SMEM>>>(
        a16, wq, bqkv);

    // 2) FA2-style attention (fp16, 64-row Q tiles, 2 CTAs/SM)
    attn_mma_kernel<<<dim3(S_LEN / ATQ, NH, BATCH), 128, ATTN_SMEM>>>(
        q16, k16, v16, a16);

    // 3) out = attn @ W_out + b_out  (fp16)
    gemm_mma_kernel<<<dim3(EMB / 128, MROWS / 128), 256, GEMM_SMEM>>>(
        EMB, a16, wo, bout, out);
}

// round 16
// speedup vs baseline: 1.2342x; 1.0379x over previous
#include <cuda_runtime.h>
#include <cuda_fp16.h>
#include <cstdint>

#define S_LEN 2048
#define EMB   2048
#define NH    16
#define DH    128
#define BATCH 2
#define MROWS (BATCH * S_LEN)   // 4096
#define GK    2048              // K for both projection GEMMs

// ---------------------------------------------------------------------------
// Device scratch (no cudaMalloc allowed)
// ---------------------------------------------------------------------------
__device__ __half g_a16[(size_t)MROWS * GK];              // A operand (x, then attn-out), fp16
__device__ __half g_wq[(size_t)(3 * EMB) * GK];           // W_qkv^T fp16 [6144,2048]
__device__ __half g_wo[(size_t)EMB * GK];                 // W_out^T fp16 [2048,2048]
// per-head Q/K/V fp16 (single-rounded), layout [B, H, S, DH]
// Q pre-scaled by log2(e)/sqrt(dh) so softmax runs in exp2 domain directly.
#define QKV_ELEMS ((size_t)BATCH * NH * S_LEN * DH)
__device__ __half g_q16[QKV_ELEMS];
__device__ __half g_k16[QKV_ELEMS];
__device__ __half g_v16[QKV_ELEMS];

// ---------------------------------------------------------------------------
// PTX helpers (plain sm_80+ instructions only)
// ---------------------------------------------------------------------------
__device__ __forceinline__ uint32_t smem_to_u32(const void* p) {
    uint32_t a;
    asm("{ .reg .u64 t; cvta.to.shared.u64 t, %1; cvt.u32.u64 %0, t; }"
        : "=r"(a) : "l"(p));
    return a;
}

__device__ __forceinline__ void cp_async16(uint32_t saddr, const void* gaddr) {
    asm volatile("cp.async.cg.shared.global [%0], [%1], 16;"
        :: "r"(saddr), "l"(gaddr) : "memory");
}
#define CP_COMMIT() asm volatile("cp.async.commit_group;" ::: "memory")
#define CP_WAIT(n)  asm volatile("cp.async.wait_group %0;" :: "n"(n) : "memory")

__device__ __forceinline__ void ldsm_x4(uint32_t* r, uint32_t addr) {
    asm volatile("ldmatrix.sync.aligned.m8n8.x4.shared.b16 {%0,%1,%2,%3}, [%4];"
        : "=r"(r[0]), "=r"(r[1]), "=r"(r[2]), "=r"(r[3]) : "r"(addr));
}
__device__ __forceinline__ void ldsm_x4_t(uint32_t* r, uint32_t addr) {
    asm volatile("ldmatrix.sync.aligned.m8n8.x4.trans.shared.b16 {%0,%1,%2,%3}, [%4];"
        : "=r"(r[0]), "=r"(r[1]), "=r"(r[2]), "=r"(r[3]) : "r"(addr));
}

// fp16 MMA (all tensor work)
__device__ __forceinline__ void mma16816h(float* d, const uint32_t* a,
                                          const uint32_t* b) {
    asm volatile(
        "mma.sync.aligned.m16n8k16.row.col.f32.f16.f16.f32 "
        "{%0,%1,%2,%3}, {%4,%5,%6,%7}, {%8,%9}, {%0,%1,%2,%3};"
        : "+f"(d[0]), "+f"(d[1]), "+f"(d[2]), "+f"(d[3])
        : "r"(a[0]), "r"(a[1]), "r"(a[2]), "r"(a[3]), "r"(b[0]), "r"(b[1]));
}

// Fast 2^t on FMA/ALU pipes only (no MUFU, no CVT). |rel err| < 3e-6.
__device__ __forceinline__ float exp2_fast(float t) {
    t = fmaxf(t, -126.0f);
    const float MAGIC = 12582912.0f;          // 2^23 + 2^22
    float z = t + MAGIC;
    int i = __float_as_int(z);
    float r = z - MAGIC;
    float f = t - r;                          // f in [-0.5, 0.5]
    float p = 1.3333558146e-3f;
    p = fmaf(p, f, 9.6181291076e-3f);
    p = fmaf(p, f, 5.5504108664e-2f);
    p = fmaf(p, f, 2.4022650696e-1f);
    p = fmaf(p, f, 6.9314718056e-1f);
    p = fmaf(p, f, 1.0f);
    int eb = (i + (127 - 0x4B400000)) << 23;
    return p * __int_as_float(eb);
}

__device__ __forceinline__ uint32_t h2u(__half2 v) {
    return *(uint32_t*)&v;
}

#define SOFTMAX_SCALE 0.12751744f     // log2(e) / sqrt(128)

// ---------------------------------------------------------------------------
// Conversion kernels
// ---------------------------------------------------------------------------
__global__ __launch_bounds__(256) void to_half_kernel(
    const float* __restrict__ in, __half* __restrict__ out, int n)
{
    int i = blockIdx.x * blockDim.x + threadIdx.x;
    int stride = gridDim.x * blockDim.x;
    for (; i < n; i += stride) out[i] = __float2half(in[i]);
}

// W[K,N] row-major -> T[N,K] fp16 (single rounding)
__global__ __launch_bounds__(256) void transpose_half_kernel(
    const float* __restrict__ W, __half* __restrict__ T, int K, int N)
{
    __shared__ float t[32][33];
    const int nb = blockIdx.x * 32;
    const int kb = blockIdx.y * 32;
    const int x = threadIdx.x, y = threadIdx.y;   // block (32,8)
    #pragma unroll
    for (int j = 0; j < 32; j += 8)
        t[y + j][x] = W[(size_t)(kb + y + j) * N + nb + x];
    __syncthreads();
    #pragma unroll
    for (int j = 0; j < 32; j += 8)
        T[(size_t)(nb + y + j) * K + kb + x] = __float2half(t[x][y + j]);
}

// ---------------------------------------------------------------------------
// fp16 HMMA mainloop (R12 geometry: 2 CTA/SM) with HOISTED ldsm addresses:
// all 24 stage-relative ldsm offsets precomputed before the K-loop.
// Block 128x128, 8 warps (2x4), warp tile 64x32, K-chunk 64, 2-stage buffer.
// ---------------------------------------------------------------------------
#define GBK   64
#define NCHUNK (GK / GBK)
#define TBYTES 16384
#define STAGE  (2 * TBYTES)          // 32 KB (A + B)
#define GEMM_SMEM (2 * STAGE)        // 64 KB

template <typename Epilogue>
__device__ __forceinline__ void gemm_mainloop(
    char* gsm,
    const __half* __restrict__ A, const __half* __restrict__ B,
    const float* __restrict__ bias, int bx, int by, Epilogue epi)
{
    const uint32_t sb = smem_to_u32(gsm);
    const int tid = threadIdx.x;
    const int w = tid >> 5, l = tid & 31;
    const int warp_m = w >> 2, warp_n = w & 3;

    const __half* srcs[2] = {
        A + (size_t)(by * 128) * GK,
        B + (size_t)(bx * 128) * GK };

    // ---- precompute stage-relative ldsm offsets (loop-invariant) ----------
    uint32_t aoff[4][4], boff[4][2];
    #pragma unroll
    for (int kk = 0; kk < 4; kk++) {
        const int kb = kk * 32;
        #pragma unroll
        for (int mt = 0; mt < 4; mt++) {
            const int row = warp_m * 64 + mt * 16 + (l & 15);
            const int bc = kb + ((l >> 4) << 4);
            aoff[kk][mt] = row * 128 + (bc ^ ((row & 7) << 4));
        }
        #pragma unroll
        for (int np = 0; np < 2; np++) {
            const int g = l >> 3, idx = l & 7;
            const int row = warp_n * 32 + np * 16 + ((g >> 1) << 3) + idx;
            const int bc = kb + ((g & 1) << 4);
            boff[kk][np] = TBYTES + row * 128 + (bc ^ ((row & 7) << 4));
        }
    }

    float acc[4][4][4];
    #pragma unroll
    for (int nt = 0; nt < 4; nt++) {
        const int n = bx * 128 + warp_n * 32 + nt * 8 + ((l & 3) << 1);
        const float b0 = bias[n], b1 = bias[n + 1];
        #pragma unroll
        for (int mt = 0; mt < 4; mt++) {
            acc[mt][nt][0] = b0; acc[mt][nt][1] = b1;
            acc[mt][nt][2] = b0; acc[mt][nt][3] = b1;
        }
    }

    auto load_chunk = [&](int kt) {
        const uint32_t st = sb + (kt & 1) * STAGE;
        const size_t kofs = (size_t)kt * GBK;
        #pragma unroll
        for (int a = 0; a < 2; a++) {
            const char* g = (const char*)(srcs[a] + kofs);
            #pragma unroll
            for (int j = 0; j < 4; j++) {
                const int u = tid + 256 * j;
                const int r = u >> 3;
                const int cu = u & 7;
                const uint32_t off = r * 128 + ((cu ^ (r & 7)) << 4);
                cp_async16(st + a * TBYTES + off,
                           g + (size_t)r * (GK * 2) + (cu << 4));
            }
        }
        CP_COMMIT();
    };

    load_chunk(0);

    for (int kt = 0; kt < NCHUNK; kt++) {
        if (kt + 1 < NCHUNK) { load_chunk(kt + 1); CP_WAIT(1); }
        else                 { CP_WAIT(0); }
        __syncthreads();

        const uint32_t st = sb + (kt & 1) * STAGE;

        #pragma unroll
        for (int kk = 0; kk < 4; kk++) {
            uint32_t af[4][4];
            #pragma unroll
            for (int mt = 0; mt < 4; mt++)
                ldsm_x4(af[mt], st + aoff[kk][mt]);

            uint32_t bf[2][4];
            #pragma unroll
            for (int np = 0; np < 2; np++)
                ldsm_x4(bf[np], st + boff[kk][np]);

            #pragma unroll
            for (int mt = 0; mt < 4; mt++)
                #pragma unroll
                for (int nt = 0; nt < 4; nt++)
                    mma16816h(acc[mt][nt], af[mt], &bf[nt >> 1][(nt & 1) * 2]);
        }
        __syncthreads();
    }

    epi(acc, warp_m, warp_n, l);
}

// GEMM2: plain fp32 output C = A*B^T + bias
__global__ __launch_bounds__(256, 2) void gemm_mma_kernel(
    int N,
    const __half* __restrict__ A, const __half* __restrict__ B,
    const float* __restrict__ bias, float* __restrict__ C)
{
    extern __shared__ char gsm[];
    const int bx = blockIdx.x, by = blockIdx.y;
    gemm_mainloop(gsm, A, B, bias, bx, by,
        [&](float acc[4][4][4], int warp_m, int warp_n, int l) {
            #pragma unroll
            for (int mt = 0; mt < 4; mt++) {
                const int m = by * 128 + warp_m * 64 + mt * 16 + (l >> 2);
                float* c0 = C + (size_t)m * N + bx * 128 + warp_n * 32 + ((l & 3) << 1);
                #pragma unroll
                for (int nt = 0; nt < 4; nt++) {
                    *(float2*)(c0 + nt * 8) =
                        make_float2(acc[mt][nt][0], acc[mt][nt][1]);
                    *(float2*)(c0 + (size_t)8 * N + nt * 8) =
                        make_float2(acc[mt][nt][2], acc[mt][nt][3]);
                }
            }
        });
}

// GEMM1 fused: writes per-head fp16 Q (pre-scaled), K, V (single-rounded).
__global__ __launch_bounds__(256, 2) void gemm_qkv_kernel(
    const __half* __restrict__ A, const __half* __restrict__ B,
    const float* __restrict__ bias)
{
    extern __shared__ char gsm[];
    const int bx = blockIdx.x, by = blockIdx.y;
    const int region = bx % 3;        // 0=q, 1=k, 2=v
    const int head   = bx / 3;
    __half* H = (region == 0) ? g_q16 : (region == 1) ? g_k16 : g_v16;
    const float scl = (region == 0) ? SOFTMAX_SCALE : 1.0f;

    gemm_mainloop(gsm, A, B, bias, bx, by,
        [&](float acc[4][4][4], int warp_m, int warp_n, int l) {
            #pragma unroll
            for (int mt = 0; mt < 4; mt++) {
                const int m = by * 128 + warp_m * 64 + mt * 16 + (l >> 2);
                const int b = m >> 11, s = m & (S_LEN - 1);
                const size_t base =
                    (((size_t)(b * NH + head)) * S_LEN + s) * DH;
                #pragma unroll
                for (int nt = 0; nt < 4; nt++) {
                    const int d = warp_n * 32 + nt * 8 + ((l & 3) << 1);
                    const __half2 h0 = __floats2half2_rn(acc[mt][nt][0] * scl,
                                                         acc[mt][nt][1] * scl);
                    const __half2 h1 = __floats2half2_rn(acc[mt][nt][2] * scl,
                                                         acc[mt][nt][3] * scl);
                    *(__half2*)(H + base + d) = h0;
                    *(__half2*)(H + base + (size_t)8 * DH + d) = h1;
                }
            }
        });
}

// ---------------------------------------------------------------------------
// FA2-style tensor-core attention (R15 config — empirically best):
// fp16 single-term, Q-tile 64, K-tile 64, 4 warps, 112 KB smem, 2 CTAs/SM.
//   QK: Q * K (Q pre-scaled) ; PV: P * V
// Each warp owns 16 Q rows (QK 16x64, PV 16x128). 3-stage KV pipeline.
// ---------------------------------------------------------------------------
#define ATQ 64
#define AKT 64
#define ANT (S_LEN / AKT)             // 32

#define ASM_Q  0                      // 16384 bytes (64 rows x 256B)
#define ASM_KV 16384                  // 3 stages x 32768 (K 16KB | V 16KB)
#define KVSTAGE 32768
#define ATTN_SMEM (16384 + 3 * KVSTAGE)  // 114688 (112 KB)

#define SWZ(row, cu) ((row) * 256 + ((((cu) ^ ((row) & 7))) << 4))

__global__ __launch_bounds__(128, 2) void attn_mma_kernel(
    const __half* __restrict__ q16, const __half* __restrict__ k16,
    const __half* __restrict__ v16,
    __half* __restrict__ outA)
{
    extern __shared__ char gsm[];
    const uint32_t sb = smem_to_u32(gsm);
    const int tid = threadIdx.x;
    const int w = tid >> 5, l = tid & 31;
    const int qt = blockIdx.x, h = blockIdx.y, b = blockIdx.z;

    const size_t head = ((size_t)(b * NH + h)) * S_LEN * DH;
    const __half* Q_g = q16 + head + (size_t)qt * ATQ * DH;

    auto load_kv = [&](int t) {
        const uint32_t st = sb + ASM_KV + (t % 3) * KVSTAGE;
        const size_t base = head + (size_t)t * AKT * DH;
        const __half* srcs[2] = {k16 + base, v16 + base};
        #pragma unroll
        for (int a = 0; a < 2; a++) {
            #pragma unroll
            for (int j = 0; j < 8; j++) {       // 64 rows x 16 units = 1024
                const int u = tid + 128 * j;
                const int row = u >> 4, cu = u & 15;
                cp_async16(st + a * 16384 + SWZ(row, cu),
                           (const char*)srcs[a] + (size_t)row * 256 + cu * 16);
            }
        }
        CP_COMMIT();
    };

    // Q loads committed together with KV(0) as group 0.
    #pragma unroll
    for (int j = 0; j < 8; j++) {                // 64 rows x 16 units = 1024
        const int u = tid + 128 * j;
        const int row = u >> 4, cu = u & 15;
        cp_async16(sb + ASM_Q + SWZ(row, cu),
                   (const char*)Q_g + (size_t)row * 256 + cu * 16);
    }
    load_kv(0);
    load_kv(1);

    // Wait for group 0 (Q + KV0), then cache ALL Q fragments in registers.
    CP_WAIT(1);
    __syncthreads();
    uint32_t qf[8][4];
    #pragma unroll
    for (int kk = 0; kk < 8; kk++) {
        const int row = w * 16 + (l & 15);
        const int cu = kk * 2 + (l >> 4);
        ldsm_x4(qf[kk], sb + ASM_Q + SWZ(row, cu));
    }

    float m0 = -1e9f, m1 = -1e9f, ls0 = 0.f, ls1 = 0.f;
    float O[16][4];
    #pragma unroll
    for (int nt = 0; nt < 16; nt++)
        #pragma unroll
        for (int c = 0; c < 4; c++) O[nt][c] = 0.f;

    for (int t = 0; t < ANT; t++) {
        if (t > 0) {
            if (t + 1 < ANT) { CP_WAIT(1); } else { CP_WAIT(0); }
            __syncthreads();
        }
        if (t + 2 < ANT) load_kv(t + 2);

        const uint32_t stg = sb + ASM_KV + (t % 3) * KVSTAGE;

        // ---- QK: sacc[8][4], warp tile 16x64, Q from registers -------------
        float sacc[8][4];
        #pragma unroll
        for (int nt = 0; nt < 8; nt++)
            #pragma unroll
            for (int c = 0; c < 4; c++) sacc[nt][c] = 0.f;

        #pragma unroll
        for (int kk = 0; kk < 8; kk++) {
            uint32_t kf[4][4];
            #pragma unroll
            for (int np = 0; np < 4; np++) {
                const int g = l >> 3, idx = l & 7;
                const int krow = np * 16 + ((g >> 1) << 3) + idx;
                const int bcu = kk * 2 + (g & 1);
                ldsm_x4(kf[np], stg + SWZ(krow, bcu));
            }
            #pragma unroll
            for (int nt = 0; nt < 8; nt++)
                mma16816h(sacc[nt], qf[kk], &kf[nt >> 1][(nt & 1) * 2]);
        }

        // ---- softmax in registers (scores already in exp2 domain) ----------
        float mx0 = sacc[0][0], mx1 = sacc[0][2];
        #pragma unroll
        for (int nt = 0; nt < 8; nt++) {
            mx0 = fmaxf(mx0, fmaxf(sacc[nt][0], sacc[nt][1]));
            mx1 = fmaxf(mx1, fmaxf(sacc[nt][2], sacc[nt][3]));
        }
        mx0 = fmaxf(mx0, __shfl_xor_sync(0xffffffffu, mx0, 1));
        mx0 = fmaxf(mx0, __shfl_xor_sync(0xffffffffu, mx0, 2));
        mx1 = fmaxf(mx1, __shfl_xor_sync(0xffffffffu, mx1, 1));
        mx1 = fmaxf(mx1, __shfl_xor_sync(0xffffffffu, mx1, 2));
        const float mn0 = fmaxf(m0, mx0);
        const float mn1 = fmaxf(m1, mx1);

        uint32_t ph[4][4];
        float s0 = 0.f, s1 = 0.f;
        #pragma unroll
        for (int nt = 0; nt < 8; nt++) {
            const float p0 = exp2_fast(sacc[nt][0] - mn0);
            const float p1 = exp2_fast(sacc[nt][1] - mn0);
            const float p2 = exp2_fast(sacc[nt][2] - mn1);
            const float p3 = exp2_fast(sacc[nt][3] - mn1);
            s0 += p0 + p1;
            s1 += p2 + p3;
            const __half2 h01 = __floats2half2_rn(p0, p1);
            const __half2 h23 = __floats2half2_rn(p2, p3);
            const int kk = nt >> 1, base = (nt & 1) * 2;
            ph[kk][base]     = h2u(h01);
            ph[kk][base + 1] = h2u(h23);
        }
        s0 += __shfl_xor_sync(0xffffffffu, s0, 1);
        s0 += __shfl_xor_sync(0xffffffffu, s0, 2);
        s1 += __shfl_xor_sync(0xffffffffu, s1, 1);
        s1 += __shfl_xor_sync(0xffffffffu, s1, 2);
        const float f0 = exp2_fast(m0 - mn0);
        const float f1 = exp2_fast(m1 - mn1);
        ls0 = ls0 * f0 + s0;
        ls1 = ls1 * f1 + s1;
        m0 = mn0; m1 = mn1;

        #pragma unroll
        for (int nt = 0; nt < 16; nt++) {
            O[nt][0] *= f0; O[nt][1] *= f0;
            O[nt][2] *= f1; O[nt][3] *= f1;
        }

        // ---- PV: warp tile 16x128, P (16x64) from registers -----------------
        const uint32_t sV = stg + 16384;
        #pragma unroll
        for (int kk = 0; kk < 4; kk++) {
            #pragma unroll
            for (int np = 0; np < 8; np++) {
                uint32_t vb[4];
                const int mat = l >> 3, idx = l & 7;
                const int key = kk * 16 + ((mat & 1) << 3) + idx;
                const int cu = np * 2 + (mat >> 1);
                ldsm_x4_t(vb, sV + SWZ(key, cu));
                mma16816h(O[np * 2 + 0], ph[kk], &vb[0]);
                mma16816h(O[np * 2 + 1], ph[kk], &vb[2]);
            }
        }
    }

    // ---- epilogue: normalize, write GEMM2's A (fp16) ----------------------
    const float inv0 = 1.f / ls0;
    const float inv1 = 1.f / ls1;
    const int row0 = qt * ATQ + w * 16 + (l >> 2);
    const size_t s0o = (size_t)(b * S_LEN + row0) * EMB + h * DH;
    #pragma unroll
    for (int nt = 0; nt < 16; nt++) {
        const int col = nt * 8 + ((l & 3) << 1);
        const __half2 h0 = __floats2half2_rn(O[nt][0] * inv0, O[nt][1] * inv0);
        const __half2 h1 = __floats2half2_rn(O[nt][2] * inv1, O[nt][3] * inv1);
        *(__half2*)(outA + s0o + col) = h0;
        *(__half2*)(outA + s0o + (size_t)8 * EMB + col) = h1;
    }
}

// ---------------------------------------------------------------------------
extern "C" void kernel_launch(void* const* d_in, const int* in_sizes, int n_in,
                              void* d_out, int out_size)
{
    (void)in_sizes; (void)n_in; (void)out_size;
    const float* x    = (const float*)d_in[0];
    const float* Wqkv = (const float*)d_in[1];
    const float* bqkv = (const float*)d_in[2];
    const float* Wout = (const float*)d_in[3];
    const float* bout = (const float*)d_in[4];
    float* out = (float*)d_out;

    __half *a16, *wq, *wo, *q16, *k16, *v16;
    cudaGetSymbolAddress((void**)&a16, g_a16);
    cudaGetSymbolAddress((void**)&wq, g_wq);
    cudaGetSymbolAddress((void**)&wo, g_wo);
    cudaGetSymbolAddress((void**)&q16, g_q16);
    cudaGetSymbolAddress((void**)&k16, g_k16);
    cudaGetSymbolAddress((void**)&v16, g_v16);

    cudaFuncSetAttribute(gemm_mma_kernel,
                         cudaFuncAttributeMaxDynamicSharedMemorySize, GEMM_SMEM);
    cudaFuncSetAttribute(gemm_qkv_kernel,
                         cudaFuncAttributeMaxDynamicSharedMemorySize, GEMM_SMEM);
    cudaFuncSetAttribute(attn_mma_kernel,
                         cudaFuncAttributeMaxDynamicSharedMemorySize, ATTN_SMEM);

    // 0) conversions (inputs only)
    to_half_kernel<<<2048, 256>>>(x, a16, MROWS * EMB);
    transpose_half_kernel<<<dim3((3 * EMB) / 32, GK / 32), dim3(32, 8)>>>(
        Wqkv, wq, GK, 3 * EMB);
    transpose_half_kernel<<<dim3(EMB / 32, GK / 32), dim3(32, 8)>>>(
        Wout, wo, GK, EMB);

    // 1) qkv projection (fp16) fused with per-head write (Q pre-scaled)
    gemm_qkv_kernel<<<dim3((3 * EMB) / 128, MROWS / 128), 256, GEMM_SMEM>>>(
        a16, wq, bqkv);

    // 2) FA2-style attention (fp16, 64-row Q tiles, 2 CTAs/SM)
    attn_mma_kernel<<<dim3(S_LEN / ATQ, NH, BATCH), 128, ATTN_SMEM>>>(
        q16, k16, v16, a16);

    // 3) out = attn @ W_out + b_out  (fp16)
    gemm_mma_kernel<<<dim3(EMB / 128, MROWS / 128), 256, GEMM_SMEM>>>(
        EMB, a16, wo, bout, out);
}

// round 17
// speedup vs baseline: 1.2439x; 1.0078x over previous
#include <cuda_runtime.h>
#include <cuda_fp16.h>
#include <cstdint>

#define S_LEN 2048
#define EMB   2048
#define NH    16
#define DH    128
#define BATCH 2
#define MROWS (BATCH * S_LEN)   // 4096
#define GK    2048              // K for both projection GEMMs

// ---------------------------------------------------------------------------
// Device scratch (no cudaMalloc allowed)
// ---------------------------------------------------------------------------
__device__ __half g_a16[(size_t)MROWS * GK];              // A operand (x, then attn-out), fp16
__device__ __half g_wq[(size_t)(3 * EMB) * GK];           // W_qkv^T fp16 [6144,2048]
__device__ __half g_wo[(size_t)EMB * GK];                 // W_out^T fp16 [2048,2048]
// per-head Q/K/V fp16 (single-rounded), layout [B, H, S, DH]
// Q pre-scaled by log2(e)/sqrt(dh) so softmax runs in exp2 domain directly.
#define QKV_ELEMS ((size_t)BATCH * NH * S_LEN * DH)
__device__ __half g_q16[QKV_ELEMS];
__device__ __half g_k16[QKV_ELEMS];
__device__ __half g_v16[QKV_ELEMS];

// ---------------------------------------------------------------------------
// PTX helpers (plain sm_80+ instructions only)
// ---------------------------------------------------------------------------
__device__ __forceinline__ uint32_t smem_to_u32(const void* p) {
    uint32_t a;
    asm("{ .reg .u64 t; cvta.to.shared.u64 t, %1; cvt.u32.u64 %0, t; }"
        : "=r"(a) : "l"(p));
    return a;
}

__device__ __forceinline__ void cp_async16(uint32_t saddr, const void* gaddr) {
    asm volatile("cp.async.cg.shared.global [%0], [%1], 16;"
        :: "r"(saddr), "l"(gaddr) : "memory");
}
#define CP_COMMIT() asm volatile("cp.async.commit_group;" ::: "memory")
#define CP_WAIT(n)  asm volatile("cp.async.wait_group %0;" :: "n"(n) : "memory")

__device__ __forceinline__ void ldsm_x4(uint32_t* r, uint32_t addr) {
    asm volatile("ldmatrix.sync.aligned.m8n8.x4.shared.b16 {%0,%1,%2,%3}, [%4];"
        : "=r"(r[0]), "=r"(r[1]), "=r"(r[2]), "=r"(r[3]) : "r"(addr));
}
__device__ __forceinline__ void ldsm_x4_t(uint32_t* r, uint32_t addr) {
    asm volatile("ldmatrix.sync.aligned.m8n8.x4.trans.shared.b16 {%0,%1,%2,%3}, [%4];"
        : "=r"(r[0]), "=r"(r[1]), "=r"(r[2]), "=r"(r[3]) : "r"(addr));
}

// fp16 MMA (all tensor work)
__device__ __forceinline__ void mma16816h(float* d, const uint32_t* a,
                                          const uint32_t* b) {
    asm volatile(
        "mma.sync.aligned.m16n8k16.row.col.f32.f16.f16.f32 "
        "{%0,%1,%2,%3}, {%4,%5,%6,%7}, {%8,%9}, {%0,%1,%2,%3};"
        : "+f"(d[0]), "+f"(d[1]), "+f"(d[2]), "+f"(d[3])
        : "r"(a[0]), "r"(a[1]), "r"(a[2]), "r"(a[3]), "r"(b[0]), "r"(b[1]));
}

// Fast 2^t on FMA/ALU pipes only (no MUFU, no CVT). |rel err| < 3e-6.
__device__ __forceinline__ float exp2_fast(float t) {
    t = fmaxf(t, -126.0f);
    const float MAGIC = 12582912.0f;          // 2^23 + 2^22
    float z = t + MAGIC;
    int i = __float_as_int(z);
    float r = z - MAGIC;
    float f = t - r;                          // f in [-0.5, 0.5]
    float p = 1.3333558146e-3f;
    p = fmaf(p, f, 9.6181291076e-3f);
    p = fmaf(p, f, 5.5504108664e-2f);
    p = fmaf(p, f, 2.4022650696e-1f);
    p = fmaf(p, f, 6.9314718056e-1f);
    p = fmaf(p, f, 1.0f);
    int eb = (i + (127 - 0x4B400000)) << 23;
    return p * __int_as_float(eb);
}

__device__ __forceinline__ uint32_t h2u(__half2 v) {
    return *(uint32_t*)&v;
}

#define SOFTMAX_SCALE 0.12751744f     // log2(e) / sqrt(128)

// ---------------------------------------------------------------------------
// Conversion kernels
// ---------------------------------------------------------------------------
__global__ __launch_bounds__(256) void to_half_kernel(
    const float* __restrict__ in, __half* __restrict__ out, int n)
{
    int i = blockIdx.x * blockDim.x + threadIdx.x;
    int stride = gridDim.x * blockDim.x;
    for (; i < n; i += stride) out[i] = __float2half(in[i]);
}

// W[K,N] row-major -> T[N,K] fp16 (single rounding)
__global__ __launch_bounds__(256) void transpose_half_kernel(
    const float* __restrict__ W, __half* __restrict__ T, int K, int N)
{
    __shared__ float t[32][33];
    const int nb = blockIdx.x * 32;
    const int kb = blockIdx.y * 32;
    const int x = threadIdx.x, y = threadIdx.y;   // block (32,8)
    #pragma unroll
    for (int j = 0; j < 32; j += 8)
        t[y + j][x] = W[(size_t)(kb + y + j) * N + nb + x];
    __syncthreads();
    #pragma unroll
    for (int j = 0; j < 32; j += 8)
        T[(size_t)(nb + y + j) * K + kb + x] = __float2half(t[x][y + j]);
}

// ---------------------------------------------------------------------------
// fp16 HMMA mainloop (R16: 2 CTA/SM, hoisted ldsm offsets):
// Block 128x128, 8 warps (2x4), warp tile 64x32, K-chunk 64, 2-stage buffer.
// ---------------------------------------------------------------------------
#define GBK   64
#define NCHUNK (GK / GBK)
#define TBYTES 16384
#define STAGE  (2 * TBYTES)          // 32 KB (A + B)
#define GEMM_SMEM (2 * STAGE)        // 64 KB

template <typename Epilogue>
__device__ __forceinline__ void gemm_mainloop(
    char* gsm,
    const __half* __restrict__ A, const __half* __restrict__ B,
    const float* __restrict__ bias, int bx, int by, Epilogue epi)
{
    const uint32_t sb = smem_to_u32(gsm);
    const int tid = threadIdx.x;
    const int w = tid >> 5, l = tid & 31;
    const int warp_m = w >> 2, warp_n = w & 3;

    const __half* srcs[2] = {
        A + (size_t)(by * 128) * GK,
        B + (size_t)(bx * 128) * GK };

    // ---- precompute stage-relative ldsm offsets (loop-invariant) ----------
    uint32_t aoff[4][4], boff[4][2];
    #pragma unroll
    for (int kk = 0; kk < 4; kk++) {
        const int kb = kk * 32;
        #pragma unroll
        for (int mt = 0; mt < 4; mt++) {
            const int row = warp_m * 64 + mt * 16 + (l & 15);
            const int bc = kb + ((l >> 4) << 4);
            aoff[kk][mt] = row * 128 + (bc ^ ((row & 7) << 4));
        }
        #pragma unroll
        for (int np = 0; np < 2; np++) {
            const int g = l >> 3, idx = l & 7;
            const int row = warp_n * 32 + np * 16 + ((g >> 1) << 3) + idx;
            const int bc = kb + ((g & 1) << 4);
            boff[kk][np] = TBYTES + row * 128 + (bc ^ ((row & 7) << 4));
        }
    }

    float acc[4][4][4];
    #pragma unroll
    for (int nt = 0; nt < 4; nt++) {
        const int n = bx * 128 + warp_n * 32 + nt * 8 + ((l & 3) << 1);
        const float b0 = bias[n], b1 = bias[n + 1];
        #pragma unroll
        for (int mt = 0; mt < 4; mt++) {
            acc[mt][nt][0] = b0; acc[mt][nt][1] = b1;
            acc[mt][nt][2] = b0; acc[mt][nt][3] = b1;
        }
    }

    auto load_chunk = [&](int kt) {
        const uint32_t st = sb + (kt & 1) * STAGE;
        const size_t kofs = (size_t)kt * GBK;
        #pragma unroll
        for (int a = 0; a < 2; a++) {
            const char* g = (const char*)(srcs[a] + kofs);
            #pragma unroll
            for (int j = 0; j < 4; j++) {
                const int u = tid + 256 * j;
                const int r = u >> 3;
                const int cu = u & 7;
                const uint32_t off = r * 128 + ((cu ^ (r & 7)) << 4);
                cp_async16(st + a * TBYTES + off,
                           g + (size_t)r * (GK * 2) + (cu << 4));
            }
        }
        CP_COMMIT();
    };

    load_chunk(0);

    for (int kt = 0; kt < NCHUNK; kt++) {
        if (kt + 1 < NCHUNK) { load_chunk(kt + 1); CP_WAIT(1); }
        else                 { CP_WAIT(0); }
        __syncthreads();

        const uint32_t st = sb + (kt & 1) * STAGE;

        #pragma unroll
        for (int kk = 0; kk < 4; kk++) {
            uint32_t af[4][4];
            #pragma unroll
            for (int mt = 0; mt < 4; mt++)
                ldsm_x4(af[mt], st + aoff[kk][mt]);

            uint32_t bf[2][4];
            #pragma unroll
            for (int np = 0; np < 2; np++)
                ldsm_x4(bf[np], st + boff[kk][np]);

            #pragma unroll
            for (int mt = 0; mt < 4; mt++)
                #pragma unroll
                for (int nt = 0; nt < 4; nt++)
                    mma16816h(acc[mt][nt], af[mt], &bf[nt >> 1][(nt & 1) * 2]);
        }
        __syncthreads();
    }

    epi(acc, warp_m, warp_n, l);
}

// GEMM2: plain fp32 output C = A*B^T + bias
__global__ __launch_bounds__(256, 2) void gemm_mma_kernel(
    int N,
    const __half* __restrict__ A, const __half* __restrict__ B,
    const float* __restrict__ bias, float* __restrict__ C)
{
    extern __shared__ char gsm[];
    const int bx = blockIdx.x, by = blockIdx.y;
    gemm_mainloop(gsm, A, B, bias, bx, by,
        [&](float acc[4][4][4], int warp_m, int warp_n, int l) {
            #pragma unroll
            for (int mt = 0; mt < 4; mt++) {
                const int m = by * 128 + warp_m * 64 + mt * 16 + (l >> 2);
                float* c0 = C + (size_t)m * N + bx * 128 + warp_n * 32 + ((l & 3) << 1);
                #pragma unroll
                for (int nt = 0; nt < 4; nt++) {
                    *(float2*)(c0 + nt * 8) =
                        make_float2(acc[mt][nt][0], acc[mt][nt][1]);
                    *(float2*)(c0 + (size_t)8 * N + nt * 8) =
                        make_float2(acc[mt][nt][2], acc[mt][nt][3]);
                }
            }
        });
}

// GEMM1 fused: writes per-head fp16 Q (pre-scaled), K, V (single-rounded).
__global__ __launch_bounds__(256, 2) void gemm_qkv_kernel(
    const __half* __restrict__ A, const __half* __restrict__ B,
    const float* __restrict__ bias)
{
    extern __shared__ char gsm[];
    const int bx = blockIdx.x, by = blockIdx.y;
    const int region = bx % 3;        // 0=q, 1=k, 2=v
    const int head   = bx / 3;
    __half* H = (region == 0) ? g_q16 : (region == 1) ? g_k16 : g_v16;
    const float scl = (region == 0) ? SOFTMAX_SCALE : 1.0f;

    gemm_mainloop(gsm, A, B, bias, bx, by,
        [&](float acc[4][4][4], int warp_m, int warp_n, int l) {
            #pragma unroll
            for (int mt = 0; mt < 4; mt++) {
                const int m = by * 128 + warp_m * 64 + mt * 16 + (l >> 2);
                const int b = m >> 11, s = m & (S_LEN - 1);
                const size_t base =
                    (((size_t)(b * NH + head)) * S_LEN + s) * DH;
                #pragma unroll
                for (int nt = 0; nt < 4; nt++) {
                    const int d = warp_n * 32 + nt * 8 + ((l & 3) << 1);
                    const __half2 h0 = __floats2half2_rn(acc[mt][nt][0] * scl,
                                                         acc[mt][nt][1] * scl);
                    const __half2 h1 = __floats2half2_rn(acc[mt][nt][2] * scl,
                                                         acc[mt][nt][3] * scl);
                    *(__half2*)(H + base + d) = h0;
                    *(__half2*)(H + base + (size_t)8 * DH + d) = h1;
                }
            }
        });
}

// ---------------------------------------------------------------------------
// FA2-style tensor-core attention (R15 config + HOISTED ldsm offsets):
// fp16 single-term, Q-tile 64, K-tile 64, 4 warps, 112 KB smem, 2 CTAs/SM.
// All 64 K/V ldsm offsets precomputed stage-relative before the mainloop.
// ---------------------------------------------------------------------------
#define ATQ 64
#define AKT 64
#define ANT (S_LEN / AKT)             // 32

#define ASM_Q  0                      // 16384 bytes (64 rows x 256B)
#define ASM_KV 16384                  // 3 stages x 32768 (K 16KB | V 16KB)
#define KVSTAGE 32768
#define ATTN_SMEM (16384 + 3 * KVSTAGE)  // 114688 (112 KB)

#define SWZ(row, cu) ((row) * 256 + ((((cu) ^ ((row) & 7))) << 4))

__global__ __launch_bounds__(128, 2) void attn_mma_kernel(
    const __half* __restrict__ q16, const __half* __restrict__ k16,
    const __half* __restrict__ v16,
    __half* __restrict__ outA)
{
    extern __shared__ char gsm[];
    const uint32_t sb = smem_to_u32(gsm);
    const int tid = threadIdx.x;
    const int w = tid >> 5, l = tid & 31;
    const int qt = blockIdx.x, h = blockIdx.y, b = blockIdx.z;

    const size_t head = ((size_t)(b * NH + h)) * S_LEN * DH;
    const __half* Q_g = q16 + head + (size_t)qt * ATQ * DH;

    auto load_kv = [&](int t) {
        const uint32_t st = sb + ASM_KV + (t % 3) * KVSTAGE;
        const size_t base = head + (size_t)t * AKT * DH;
        const __half* srcs[2] = {k16 + base, v16 + base};
        #pragma unroll
        for (int a = 0; a < 2; a++) {
            #pragma unroll
            for (int j = 0; j < 8; j++) {       // 64 rows x 16 units = 1024
                const int u = tid + 128 * j;
                const int row = u >> 4, cu = u & 15;
                cp_async16(st + a * 16384 + SWZ(row, cu),
                           (const char*)srcs[a] + (size_t)row * 256 + cu * 16);
            }
        }
        CP_COMMIT();
    };

    // Q loads committed together with KV(0) as group 0.
    #pragma unroll
    for (int j = 0; j < 8; j++) {                // 64 rows x 16 units = 1024
        const int u = tid + 128 * j;
        const int row = u >> 4, cu = u & 15;
        cp_async16(sb + ASM_Q + SWZ(row, cu),
                   (const char*)Q_g + (size_t)row * 256 + cu * 16);
    }
    load_kv(0);
    load_kv(1);

    // ---- precompute stage-relative K/V ldsm offsets (loop-invariant) ------
    uint32_t koff[8][4];     // K region at stage offset 0
    uint32_t voff[4][8];     // V region at stage offset 16384
    {
        const int g = l >> 3, idx = l & 7;
        #pragma unroll
        for (int kk = 0; kk < 8; kk++)
            #pragma unroll
            for (int np = 0; np < 4; np++) {
                const int krow = np * 16 + ((g >> 1) << 3) + idx;
                const int bcu = kk * 2 + (g & 1);
                koff[kk][np] = SWZ(krow, bcu);
            }
        const int mat = l >> 3;  // same as g
        #pragma unroll
        for (int kk = 0; kk < 4; kk++)
            #pragma unroll
            for (int np = 0; np < 8; np++) {
                const int key = kk * 16 + ((mat & 1) << 3) + idx;
                const int cu = np * 2 + (mat >> 1);
                voff[kk][np] = 16384 + SWZ(key, cu);
            }
    }

    // Wait for group 0 (Q + KV0), then cache ALL Q fragments in registers.
    CP_WAIT(1);
    __syncthreads();
    uint32_t qf[8][4];
    #pragma unroll
    for (int kk = 0; kk < 8; kk++) {
        const int row = w * 16 + (l & 15);
        const int cu = kk * 2 + (l >> 4);
        ldsm_x4(qf[kk], sb + ASM_Q + SWZ(row, cu));
    }

    float m0 = -1e9f, m1 = -1e9f, ls0 = 0.f, ls1 = 0.f;
    float O[16][4];
    #pragma unroll
    for (int nt = 0; nt < 16; nt++)
        #pragma unroll
        for (int c = 0; c < 4; c++) O[nt][c] = 0.f;

    for (int t = 0; t < ANT; t++) {
        if (t > 0) {
            if (t + 1 < ANT) { CP_WAIT(1); } else { CP_WAIT(0); }
            __syncthreads();
        }
        if (t + 2 < ANT) load_kv(t + 2);

        const uint32_t stg = sb + ASM_KV + (t % 3) * KVSTAGE;

        // ---- QK: sacc[8][4], warp tile 16x64, hoisted K offsets ------------
        float sacc[8][4];
        #pragma unroll
        for (int nt = 0; nt < 8; nt++)
            #pragma unroll
            for (int c = 0; c < 4; c++) sacc[nt][c] = 0.f;

        #pragma unroll
        for (int kk = 0; kk < 8; kk++) {
            uint32_t kf[4][4];
            #pragma unroll
            for (int np = 0; np < 4; np++)
                ldsm_x4(kf[np], stg + koff[kk][np]);
            #pragma unroll
            for (int nt = 0; nt < 8; nt++)
                mma16816h(sacc[nt], qf[kk], &kf[nt >> 1][(nt & 1) * 2]);
        }

        // ---- softmax in registers (scores already in exp2 domain) ----------
        float mx0 = sacc[0][0], mx1 = sacc[0][2];
        #pragma unroll
        for (int nt = 0; nt < 8; nt++) {
            mx0 = fmaxf(mx0, fmaxf(sacc[nt][0], sacc[nt][1]));
            mx1 = fmaxf(mx1, fmaxf(sacc[nt][2], sacc[nt][3]));
        }
        mx0 = fmaxf(mx0, __shfl_xor_sync(0xffffffffu, mx0, 1));
        mx0 = fmaxf(mx0, __shfl_xor_sync(0xffffffffu, mx0, 2));
        mx1 = fmaxf(mx1, __shfl_xor_sync(0xffffffffu, mx1, 1));
        mx1 = fmaxf(mx1, __shfl_xor_sync(0xffffffffu, mx1, 2));
        const float mn0 = fmaxf(m0, mx0);
        const float mn1 = fmaxf(m1, mx1);

        uint32_t ph[4][4];
        float s0 = 0.f, s1 = 0.f;
        #pragma unroll
        for (int nt = 0; nt < 8; nt++) {
            const float p0 = exp2_fast(sacc[nt][0] - mn0);
            const float p1 = exp2_fast(sacc[nt][1] - mn0);
            const float p2 = exp2_fast(sacc[nt][2] - mn1);
            const float p3 = exp2_fast(sacc[nt][3] - mn1);
            s0 += p0 + p1;
            s1 += p2 + p3;
            const __half2 h01 = __floats2half2_rn(p0, p1);
            const __half2 h23 = __floats2half2_rn(p2, p3);
            const int kk = nt >> 1, base = (nt & 1) * 2;
            ph[kk][base]     = h2u(h01);
            ph[kk][base + 1] = h2u(h23);
        }
        s0 += __shfl_xor_sync(0xffffffffu, s0, 1);
        s0 += __shfl_xor_sync(0xffffffffu, s0, 2);
        s1 += __shfl_xor_sync(0xffffffffu, s1, 1);
        s1 += __shfl_xor_sync(0xffffffffu, s1, 2);
        const float f0 = exp2_fast(m0 - mn0);
        const float f1 = exp2_fast(m1 - mn1);
        ls0 = ls0 * f0 + s0;
        ls1 = ls1 * f1 + s1;
        m0 = mn0; m1 = mn1;

        #pragma unroll
        for (int nt = 0; nt < 16; nt++) {
            O[nt][0] *= f0; O[nt][1] *= f0;
            O[nt][2] *= f1; O[nt][3] *= f1;
        }

        // ---- PV: warp tile 16x128, hoisted V offsets ------------------------
        #pragma unroll
        for (int kk = 0; kk < 4; kk++) {
            #pragma unroll
            for (int np = 0; np < 8; np++) {
                uint32_t vb[4];
                ldsm_x4_t(vb, stg + voff[kk][np]);
                mma16816h(O[np * 2 + 0], ph[kk], &vb[0]);
                mma16816h(O[np * 2 + 1], ph[kk], &vb[2]);
            }
        }
    }

    // ---- epilogue: normalize, write GEMM2's A (fp16) ----------------------
    const float inv0 = 1.f / ls0;
    const float inv1 = 1.f / ls1;
    const int row0 = qt * ATQ + w * 16 + (l >> 2);
    const size_t s0o = (size_t)(b * S_LEN + row0) * EMB + h * DH;
    #pragma unroll
    for (int nt = 0; nt < 16; nt++) {
        const int col = nt * 8 + ((l & 3) << 1);
        const __half2 h0 = __floats2half2_rn(O[nt][0] * inv0, O[nt][1] * inv0);
        const __half2 h1 = __floats2half2_rn(O[nt][2] * inv1, O[nt][3] * inv1);
        *(__half2*)(outA + s0o + col) = h0;
        *(__half2*)(outA + s0o + (size_t)8 * EMB + col) = h1;
    }
}

// ---------------------------------------------------------------------------
extern "C" void kernel_launch(void* const* d_in, const int* in_sizes, int n_in,
                              void* d_out, int out_size)
{
    (void)in_sizes; (void)n_in; (void)out_size;
    const float* x    = (const float*)d_in[0];
    const float* Wqkv = (const float*)d_in[1];
    const float* bqkv = (const float*)d_in[2];
    const float* Wout = (const float*)d_in[3];
    const float* bout = (const float*)d_in[4];
    float* out = (float*)d_out;

    __half *a16, *wq, *wo, *q16, *k16, *v16;
    cudaGetSymbolAddress((void**)&a16, g_a16);
    cudaGetSymbolAddress((void**)&wq, g_wq);
    cudaGetSymbolAddress((void**)&wo, g_wo);
    cudaGetSymbolAddress((void**)&q16, g_q16);
    cudaGetSymbolAddress((void**)&k16, g_k16);
    cudaGetSymbolAddress((void**)&v16, g_v16);

    cudaFuncSetAttribute(gemm_mma_kernel,
                         cudaFuncAttributeMaxDynamicSharedMemorySize, GEMM_SMEM);
    cudaFuncSetAttribute(gemm_qkv_kernel,
                         cudaFuncAttributeMaxDynamicSharedMemorySize, GEMM_SMEM);
    cudaFuncSetAttribute(attn_mma_kernel,
                         cudaFuncAttributeMaxDynamicSharedMemorySize, ATTN_SMEM);

    // 0) conversions (inputs only)
    to_half_kernel<<<2048, 256>>>(x, a16, MROWS * EMB);
    transpose_half_kernel<<<dim3((3 * EMB) / 32, GK / 32), dim3(32, 8)>>>(
        Wqkv, wq, GK, 3 * EMB);
    transpose_half_kernel<<<dim3(EMB / 32, GK / 32), dim3(32, 8)>>>(
        Wout, wo, GK, EMB);

    // 1) qkv projection (fp16) fused with per-head write (Q pre-scaled)
    gemm_qkv_kernel<<<dim3((3 * EMB) / 128, MROWS / 128), 256, GEMM_SMEM>>>(
        a16, wq, bqkv);

    // 2) FA2-style attention (fp16, 64-row Q tiles, 2 CTAs/SM, hoisted addrs)
    attn_mma_kernel<<<dim3(S_LEN / ATQ, NH, BATCH), 128, ATTN_SMEM>>>(
        q16, k16, v16, a16);

    // 3) out = attn @ W_out + b_out  (fp16)
    gemm_mma_kernel<<<dim3(EMB / 128, MROWS / 128), 256, GEMM_SMEM>>>(
        EMB, a16, wo, bout, out);
}